// round 1
// baseline (speedup 1.0000x reference)
#include <cuda_runtime.h>
#include <math.h>

#define MODS 3
#define HEADS 4
#define HID 256
#define EMBD 512
#define NN0 49152
#define NN1 16384
#define BB 8192
#define EE0 262144
#define EE1 131072

// ---------------- static scratch (allowed: __device__ globals) ----------------
__device__ float g_h[(size_t)NN0 * HID];      // h0 (reused as h1)
__device__ float g_s[(size_t)NN0 * HEADS];    // attention scores per source node
__device__ float g_out0[(size_t)NN1 * HID];   // block-0 GAT output
__device__ float g_gat1[(size_t)BB * HID];    // block-1 GAT output
__device__ float g_acc[(size_t)BB * HID];     // accumulated across modalities
__device__ float g_c[(size_t)EE0 * HEADS];    // per-edge coefficients alpha*val
__device__ int   g_cnt[NN1];
__device__ int   g_indptr[NN1 + 1];
__device__ int   g_wp[NN1];
__device__ int   g_order[EE0];

// ---------------- small utility kernels ----------------
__global__ void k_zero_f(float* p, int n) {
    int i = blockIdx.x * blockDim.x + threadIdx.x;
    if (i < n) p[i] = 0.f;
}
__global__ void k_zero_i(int* p, int n) {
    int i = blockIdx.x * blockDim.x + threadIdx.x;
    if (i < n) p[i] = 0;
}
__global__ void k_hist(const int* __restrict__ dst, int E, int* cnt) {
    int i = blockIdx.x * blockDim.x + threadIdx.x;
    if (i < E) atomicAdd(&cnt[dst[i]], 1);
}
// single-block exclusive scan (n <= 16384), writes indptr[0..n] and wp=indptr
__global__ void k_scan(const int* __restrict__ cnt, int n, int* indptr, int* wp) {
    __shared__ int part[1024];
    int tid = threadIdx.x;
    int per = (n + 1023) / 1024;
    int beg = tid * per;
    int end = min(beg + per, n);
    int sum = 0;
    for (int i = beg; i < end; i++) sum += cnt[i];
    part[tid] = sum;
    __syncthreads();
    for (int off = 1; off < 1024; off <<= 1) {
        int v = (tid >= off) ? part[tid - off] : 0;
        __syncthreads();
        part[tid] += v;
        __syncthreads();
    }
    int run = part[tid] - sum;  // exclusive prefix
    for (int i = beg; i < end; i++) {
        indptr[i] = run;
        wp[i] = run;
        run += cnt[i];
    }
    if (tid == 1023) indptr[n] = part[1023];
}
__global__ void k_scatter(const int* __restrict__ dst, int E, int* wp, int* order) {
    int i = blockIdx.x * blockDim.x + threadIdx.x;
    if (i < E) {
        int p = atomicAdd(&wp[dst[i]], 1);
        order[p] = i;
    }
}
// deterministic: restore ascending edge-id order within each segment
__global__ void k_sortseg(const int* __restrict__ indptr, int nseg, int* order) {
    int j = blockIdx.x * blockDim.x + threadIdx.x;
    if (j >= nseg) return;
    int b = indptr[j], e = indptr[j + 1];
    for (int i = b + 1; i < e; i++) {
        int v = order[i];
        int k = i - 1;
        while (k >= b && order[k] > v) { order[k + 1] = order[k]; k--; }
        order[k + 1] = v;
    }
}

// s[n,h] = sum_d h[n, h*64+d] * att[h*64+d]
__global__ void k_score(const float* __restrict__ h, const float* __restrict__ att,
                        float* __restrict__ s) {
    int r = blockIdx.x;
    int t = threadIdx.x;
    __shared__ float sh[256];
    sh[t] = h[(size_t)r * HID + t] * att[t];
    __syncthreads();
    for (int off = 32; off >= 1; off >>= 1) {
        if ((t & 63) < off) sh[t] += sh[t + off];
        __syncthreads();
    }
    if ((t & 63) == 0) s[(size_t)r * HEADS + (t >> 6)] = sh[t];
}

__device__ __forceinline__ float lrelu(float x) { return x > 0.f ? x : 0.2f * x; }

// per-segment softmax coefficients: c[e,h] = exp(lg-mx)/(den+1e-16) * vals[e]
__global__ void k_coef(const int* __restrict__ order, const int* __restrict__ indptr,
                       const int* __restrict__ src, const float* __restrict__ vals,
                       const float* __restrict__ s, float* __restrict__ c, int nseg) {
    int w = (blockIdx.x * blockDim.x + threadIdx.x) >> 5;
    int lane = threadIdx.x & 31;
    if (w >= nseg) return;
    int beg = indptr[w], end = indptr[w + 1];
    if (beg == end) return;
    float m0 = -1e30f, m1 = -1e30f, m2 = -1e30f, m3 = -1e30f;
    for (int p = beg + lane; p < end; p += 32) {
        int e = order[p];
        float4 sv = *(const float4*)(s + (size_t)src[e] * 4);
        m0 = fmaxf(m0, lrelu(sv.x)); m1 = fmaxf(m1, lrelu(sv.y));
        m2 = fmaxf(m2, lrelu(sv.z)); m3 = fmaxf(m3, lrelu(sv.w));
    }
    for (int off = 16; off; off >>= 1) {
        m0 = fmaxf(m0, __shfl_xor_sync(0xffffffffu, m0, off));
        m1 = fmaxf(m1, __shfl_xor_sync(0xffffffffu, m1, off));
        m2 = fmaxf(m2, __shfl_xor_sync(0xffffffffu, m2, off));
        m3 = fmaxf(m3, __shfl_xor_sync(0xffffffffu, m3, off));
    }
    float d0 = 0.f, d1 = 0.f, d2 = 0.f, d3 = 0.f;
    for (int p = beg + lane; p < end; p += 32) {
        int e = order[p];
        float4 sv = *(const float4*)(s + (size_t)src[e] * 4);
        d0 += expf(lrelu(sv.x) - m0); d1 += expf(lrelu(sv.y) - m1);
        d2 += expf(lrelu(sv.z) - m2); d3 += expf(lrelu(sv.w) - m3);
    }
    for (int off = 16; off; off >>= 1) {
        d0 += __shfl_xor_sync(0xffffffffu, d0, off);
        d1 += __shfl_xor_sync(0xffffffffu, d1, off);
        d2 += __shfl_xor_sync(0xffffffffu, d2, off);
        d3 += __shfl_xor_sync(0xffffffffu, d3, off);
    }
    float i0 = 1.f / (d0 + 1e-16f), i1 = 1.f / (d1 + 1e-16f);
    float i2 = 1.f / (d2 + 1e-16f), i3 = 1.f / (d3 + 1e-16f);
    for (int p = beg + lane; p < end; p += 32) {
        int e = order[p];
        float4 sv = *(const float4*)(s + (size_t)src[e] * 4);
        float v = vals[e];
        float4 cc;
        cc.x = expf(lrelu(sv.x) - m0) * i0 * v;
        cc.y = expf(lrelu(sv.y) - m1) * i1 * v;
        cc.z = expf(lrelu(sv.z) - m2) * i2 * v;
        cc.w = expf(lrelu(sv.w) - m3) * i3 * v;
        *(float4*)(c + (size_t)e * 4) = cc;
    }
}

// out[j, t] = sum_edges c[e, t/64] * h[src[e], t] + bias[t]
__global__ void k_reduce(const int* __restrict__ order, const int* __restrict__ indptr,
                         const int* __restrict__ src, const float* __restrict__ c,
                         const float* __restrict__ h, const float* __restrict__ bias,
                         float* __restrict__ out) {
    int j = blockIdx.x;
    int t = threadIdx.x;
    int head = t >> 6;
    __shared__ int ssrc[64];
    __shared__ float scoef[64 * 4];
    int beg = indptr[j], end = indptr[j + 1];
    float acc = 0.f;
    for (int ch = beg; ch < end; ch += 64) {
        int n = min(64, end - ch);
        if (t < n) {
            int e = order[ch + t];
            ssrc[t] = src[e];
            *(float4*)&scoef[t * 4] = *(const float4*)(c + (size_t)e * 4);
        }
        __syncthreads();
        for (int q = 0; q < n; q++)
            acc += scoef[q * 4 + head] * h[(size_t)ssrc[q] * HID + t];
        __syncthreads();
    }
    out[(size_t)j * HID + t] = acc + bias[t];
}

// ---------------- tiled SGEMM: C[M,N] = (gather(A)+abias) @ B + cbias ----------
// BM=128 BN=128 BK=8, 256 threads, 8x8 microtile. Requires M%128==0, N%128==0, K%8==0.
__global__ __launch_bounds__(256) void k_sgemm(
    const float* __restrict__ A, const int* __restrict__ gidx,
    const float* __restrict__ abias, const float* __restrict__ B,
    const float* __restrict__ cbias, float* __restrict__ C,
    int M, int N, int K) {
    __shared__ float As[8][128];
    __shared__ float Bs[8][128];
    int tid = threadIdx.x;
    int bm = blockIdx.y * 128;
    int bn = blockIdx.x * 128;
    int lrow = tid >> 1;
    int lk = (tid & 1) * 4;
    int bk = tid >> 5;
    int bcol = (tid & 31) * 4;
    int tx = tid & 15, ty = tid >> 4;
    int arow = bm + lrow;
    size_t abase = (size_t)(gidx ? gidx[arow] : arow) * K;
    float acc[8][8];
#pragma unroll
    for (int i = 0; i < 8; i++)
#pragma unroll
        for (int j = 0; j < 8; j++) acc[i][j] = 0.f;

    for (int k0 = 0; k0 < K; k0 += 8) {
        float4 av = *(const float4*)(A + abase + k0 + lk);
        if (abias) {
            float4 ab = *(const float4*)(abias + k0 + lk);
            av.x += ab.x; av.y += ab.y; av.z += ab.z; av.w += ab.w;
        }
        As[lk + 0][lrow] = av.x; As[lk + 1][lrow] = av.y;
        As[lk + 2][lrow] = av.z; As[lk + 3][lrow] = av.w;
        float4 bv = *(const float4*)(B + (size_t)(k0 + bk) * N + bn + bcol);
        *(float4*)&Bs[bk][bcol] = bv;
        __syncthreads();
#pragma unroll
        for (int kk = 0; kk < 8; kk++) {
            float4 a0 = *(float4*)&As[kk][ty * 8];
            float4 a1 = *(float4*)&As[kk][ty * 8 + 4];
            float4 b0 = *(float4*)&Bs[kk][tx * 8];
            float4 b1 = *(float4*)&Bs[kk][tx * 8 + 4];
            float ar[8] = {a0.x, a0.y, a0.z, a0.w, a1.x, a1.y, a1.z, a1.w};
            float br[8] = {b0.x, b0.y, b0.z, b0.w, b1.x, b1.y, b1.z, b1.w};
#pragma unroll
            for (int i = 0; i < 8; i++)
#pragma unroll
                for (int j = 0; j < 8; j++) acc[i][j] += ar[i] * br[j];
        }
        __syncthreads();
    }
#pragma unroll
    for (int i = 0; i < 8; i++) {
        size_t r = (size_t)(bm + ty * 8 + i) * N + bn + tx * 8;
#pragma unroll
        for (int j = 0; j < 8; j += 4) {
            float4 v;
            v.x = acc[i][j]; v.y = acc[i][j + 1]; v.z = acc[i][j + 2]; v.w = acc[i][j + 3];
            if (cbias) {
                float4 cb = *(const float4*)(cbias + bn + tx * 8 + j);
                v.x += cb.x; v.y += cb.y; v.z += cb.z; v.w += cb.w;
            }
            *(float4*)(C + r + j) = v;
        }
    }
}

// ---------------- NT GEMM: C[8192,8192] = G @ G^T, K=512 ----------------
__global__ __launch_bounds__(256) void k_dot(const float* __restrict__ G,
                                             float* __restrict__ C) {
    __shared__ float As[8][128];
    __shared__ float Bs[8][128];
    int tid = threadIdx.x;
    int bi = blockIdx.y * 128;
    int bj = blockIdx.x * 128;
    int lrow = tid >> 1;
    int lk = (tid & 1) * 4;
    int tx = tid & 15, ty = tid >> 4;
    const float* Ar = G + (size_t)(bi + lrow) * EMBD + lk;
    const float* Br = G + (size_t)(bj + lrow) * EMBD + lk;
    float acc[8][8];
#pragma unroll
    for (int i = 0; i < 8; i++)
#pragma unroll
        for (int j = 0; j < 8; j++) acc[i][j] = 0.f;

    for (int k0 = 0; k0 < EMBD; k0 += 8) {
        float4 av = *(const float4*)(Ar + k0);
        float4 bv = *(const float4*)(Br + k0);
        As[lk + 0][lrow] = av.x; As[lk + 1][lrow] = av.y;
        As[lk + 2][lrow] = av.z; As[lk + 3][lrow] = av.w;
        Bs[lk + 0][lrow] = bv.x; Bs[lk + 1][lrow] = bv.y;
        Bs[lk + 2][lrow] = bv.z; Bs[lk + 3][lrow] = bv.w;
        __syncthreads();
#pragma unroll
        for (int kk = 0; kk < 8; kk++) {
            float4 a0 = *(float4*)&As[kk][ty * 8];
            float4 a1 = *(float4*)&As[kk][ty * 8 + 4];
            float4 b0 = *(float4*)&Bs[kk][tx * 8];
            float4 b1 = *(float4*)&Bs[kk][tx * 8 + 4];
            float ar[8] = {a0.x, a0.y, a0.z, a0.w, a1.x, a1.y, a1.z, a1.w};
            float br[8] = {b0.x, b0.y, b0.z, b0.w, b1.x, b1.y, b1.z, b1.w};
#pragma unroll
            for (int i = 0; i < 8; i++)
#pragma unroll
                for (int j = 0; j < 8; j++) acc[i][j] += ar[i] * br[j];
        }
        __syncthreads();
    }
#pragma unroll
    for (int i = 0; i < 8; i++) {
        size_t r = (size_t)(bi + ty * 8 + i) * BB + bj + tx * 8;
#pragma unroll
        for (int j = 0; j < 8; j += 4) {
            float4 v;
            v.x = acc[i][j]; v.y = acc[i][j + 1]; v.z = acc[i][j + 2]; v.w = acc[i][j + 3];
            *(float4*)(C + r + j) = v;
        }
    }
}

// skip connection + interpolation accumulate
__global__ void k_accum(const float* __restrict__ out0, const int* __restrict__ res,
                        const float* __restrict__ gat1, const float* __restrict__ masks,
                        const float* __restrict__ iw, int mod, float* __restrict__ acc) {
    int b = blockIdx.x;
    int t = threadIdx.x;
    __shared__ float coef;
    __shared__ int rid;
    if (t == 0) {
        float w0 = iw[0], w1 = iw[1], w2 = iw[2];
        float mw = fmaxf(w0, fmaxf(w1, w2));
        float e0 = expf(w0 - mw), e1 = expf(w1 - mw), e2 = expf(w2 - mw);
        float ws = e0 + e1 + e2;
        float wi = (mod == 0 ? e0 : (mod == 1 ? e1 : e2)) / ws;
        float m0 = masks[b * 3 + 0], m1 = masks[b * 3 + 1], m2 = masks[b * 3 + 2];
        float msum = m0 + m1 + m2;
        float r = 1.0f + 1.0f / powf(1.0f + 3.0f, 20.0f) + 1.0f / powf(msum, 20.0f);
        r = floorf(r);
        r = r / (r + 1e-10f);
        float z0 = m0 * r, z1 = m1 * r, z2 = m2 * r;
        z0 = z0 + (1.0f - z0) * (-1e10f);
        z1 = z1 + (1.0f - z1) * (-1e10f);
        z2 = z2 + (1.0f - z2) * (-1e10f);
        float zm = fmaxf(z0, fmaxf(z1, z2));
        float x0 = expf(z0 - zm), x1 = expf(z1 - zm), x2 = expf(z2 - zm);
        float xs = x0 + x1 + x2;
        float im = (mod == 0 ? x0 : (mod == 1 ? x1 : x2)) / xs;
        coef = wi * im;
        rid = res[b];
    }
    __syncthreads();
    acc[(size_t)b * HID + t] += coef * (out0[(size_t)rid * HID + t] + gat1[(size_t)b * HID + t]);
}

__global__ void k_weights(const float* __restrict__ iw, float* __restrict__ o) {
    float w0 = iw[0], w1 = iw[1], w2 = iw[2];
    float m = fmaxf(w0, fmaxf(w1, w2));
    float e0 = expf(w0 - m), e1 = expf(w1 - m), e2 = expf(w2 - m);
    float s = e0 + e1 + e2;
    o[0] = e0 / s; o[1] = e1 / s; o[2] = e2 / s;
}

// ---------------- host side ----------------
static void build_csr(const int* dst, int E, int nseg,
                      int* cnt, int* indptr, int* wp, int* order) {
    k_zero_i<<<(nseg + 255) / 256, 256>>>(cnt, nseg);
    k_hist<<<(E + 255) / 256, 256>>>(dst, E, cnt);
    k_scan<<<1, 1024>>>(cnt, nseg, indptr, wp);
    k_scatter<<<(E + 255) / 256, 256>>>(dst, E, wp, order);
    k_sortseg<<<(nseg + 255) / 256, 256>>>(indptr, nseg, order);
}

extern "C" void kernel_launch(void* const* d_in, const int* in_sizes, int n_in,
                              void* d_out, int out_size) {
    const int*   n_id     = (const int*)d_in[0];
    const int*   src0     = (const int*)d_in[1];
    const int*   dst0     = (const int*)d_in[2];
    const int*   src1     = (const int*)d_in[3];
    const int*   dst1     = (const int*)d_in[4];
    const int*   res_n_id = (const int*)d_in[5];
    const float* vals0    = (const float*)d_in[6];
    const float* vals1    = (const float*)d_in[7];
    const float* masks    = (const float*)d_in[8];
    const float* pre_W    = (const float*)d_in[9];
    const float* pre_b    = (const float*)d_in[10];
    const float* W_gat    = (const float*)d_in[11];
    const float* att      = (const float*)d_in[12];
    const float* gat_b    = (const float*)d_in[13];
    const float* interp_w = (const float*)d_in[14];
    const float* emb_W    = (const float*)d_in[15];
    const float* emb_b    = (const float*)d_in[16];

    float* dot = (float*)d_out;
    float* emb = dot + (size_t)BB * BB;
    float* wout = emb + (size_t)BB * EMBD;

    float *h, *s, *out0, *gat1, *acc, *c;
    int *cnt, *indptr, *wp, *order;
    cudaGetSymbolAddress((void**)&h, g_h);
    cudaGetSymbolAddress((void**)&s, g_s);
    cudaGetSymbolAddress((void**)&out0, g_out0);
    cudaGetSymbolAddress((void**)&gat1, g_gat1);
    cudaGetSymbolAddress((void**)&acc, g_acc);
    cudaGetSymbolAddress((void**)&c, g_c);
    cudaGetSymbolAddress((void**)&cnt, g_cnt);
    cudaGetSymbolAddress((void**)&indptr, g_indptr);
    cudaGetSymbolAddress((void**)&wp, g_wp);
    cudaGetSymbolAddress((void**)&order, g_order);

    k_zero_f<<<(BB * HID + 255) / 256, 256>>>(acc, BB * HID);

    const int IN_SZ = 50000;
    for (int i = 0; i < MODS; i++) {
        const float* Wg  = W_gat + (size_t)i * HID * HID;
        const float* ai  = att + (size_t)i * HID;
        const float* gbi = gat_b + (size_t)i * HID;

        // ---- block 0: N0 sources -> N1 targets ----
        const int* s0 = src0 + (size_t)i * EE0;
        build_csr(dst0 + (size_t)i * EE0, EE0, NN1, cnt, indptr, wp, order);
        {   // h0 = (pre_W[i][n_id] + pre_b[i]) @ Wg
            dim3 grid(HID / 128, NN0 / 128);
            k_sgemm<<<grid, 256>>>(pre_W + (size_t)i * IN_SZ * HID,
                                   n_id + (size_t)i * NN0,
                                   pre_b + (size_t)i * HID,
                                   Wg, nullptr, h, NN0, HID, HID);
        }
        k_score<<<NN0, 256>>>(h, ai, s);
        k_coef<<<(NN1 * 32 + 255) / 256, 256>>>(order, indptr, s0,
                                                vals0 + (size_t)i * EE0, s, c, NN1);
        k_reduce<<<NN1, 256>>>(order, indptr, s0, c, h, gbi, out0);

        // ---- block 1: N1 sources -> B targets ----
        const int* s1 = src1 + (size_t)i * EE1;
        build_csr(dst1 + (size_t)i * EE1, EE1, BB, cnt, indptr, wp, order);
        {   // h1 = out0 @ Wg
            dim3 grid(HID / 128, NN1 / 128);
            k_sgemm<<<grid, 256>>>(out0, nullptr, nullptr, Wg, nullptr, h,
                                   NN1, HID, HID);
        }
        k_score<<<NN1, 256>>>(h, ai, s);
        k_coef<<<(BB * 32 + 255) / 256, 256>>>(order, indptr, s1,
                                               vals1 + (size_t)i * EE1, s, c, BB);
        k_reduce<<<BB, 256>>>(order, indptr, s1, c, h, gbi, gat1);

        // ---- skip + interpolation accumulate ----
        k_accum<<<BB, 256>>>(out0, res_n_id + (size_t)i * BB, gat1, masks,
                             interp_w, i, acc);
    }

    // emb = acc @ emb_W + emb_b
    {
        dim3 grid(EMBD / 128, BB / 128);
        k_sgemm<<<grid, 256>>>(acc, nullptr, nullptr, emb_W, emb_b, emb,
                               BB, EMBD, HID);
    }
    // dot = emb @ emb^T
    {
        dim3 grid(BB / 128, BB / 128);
        k_dot<<<grid, 256>>>(emb, dot);
    }
    k_weights<<<1, 1>>>(interp_w, wout);
}

// round 3
// speedup vs baseline: 1.3534x; 1.3534x over previous
#include <cuda_runtime.h>
#include <cuda_bf16.h>
#include <cstdint>
#include <math.h>

#define MODS 3
#define HEADS 4
#define HID 256
#define EMBD 512
#define NN0 49152
#define NN1 16384
#define BB 8192
#define EE0 262144
#define EE1 131072

// ---------------- static scratch (allowed: __device__ globals) ----------------
__device__ float g_h[(size_t)NN0 * HID];      // h0 (reused as h1)
__device__ float g_s[(size_t)NN0 * HEADS];    // attention scores per source node
__device__ float g_out0[(size_t)NN1 * HID];   // block-0 GAT output
__device__ float g_gat1[(size_t)BB * HID];    // block-1 GAT output
__device__ float g_acc[(size_t)BB * HID];     // accumulated across modalities
__device__ float g_c[(size_t)EE0 * HEADS];    // per-edge coefficients alpha*val
__device__ int   g_cnt[NN1];
__device__ int   g_indptr[NN1 + 1];
__device__ int   g_wp[NN1];
__device__ int   g_order[EE0];
__device__ __nv_bfloat16 g_ehi[(size_t)BB * EMBD];
__device__ __nv_bfloat16 g_elo[(size_t)BB * EMBD];

// ---------------- small utility kernels ----------------
__global__ void k_zero_f(float* p, int n) {
    int i = blockIdx.x * blockDim.x + threadIdx.x;
    if (i < n) p[i] = 0.f;
}
__global__ void k_zero_i(int* p, int n) {
    int i = blockIdx.x * blockDim.x + threadIdx.x;
    if (i < n) p[i] = 0;
}
__global__ void k_hist(const int* __restrict__ dst, int E, int* cnt) {
    int i = blockIdx.x * blockDim.x + threadIdx.x;
    if (i < E) atomicAdd(&cnt[dst[i]], 1);
}
// single-block exclusive scan (n <= 16384), writes indptr[0..n] and wp=indptr
__global__ void k_scan(const int* __restrict__ cnt, int n, int* indptr, int* wp) {
    __shared__ int part[1024];
    int tid = threadIdx.x;
    int per = (n + 1023) / 1024;
    int beg = tid * per;
    int end = min(beg + per, n);
    int sum = 0;
    for (int i = beg; i < end; i++) sum += cnt[i];
    part[tid] = sum;
    __syncthreads();
    for (int off = 1; off < 1024; off <<= 1) {
        int v = (tid >= off) ? part[tid - off] : 0;
        __syncthreads();
        part[tid] += v;
        __syncthreads();
    }
    int run = part[tid] - sum;  // exclusive prefix
    for (int i = beg; i < end; i++) {
        indptr[i] = run;
        wp[i] = run;
        run += cnt[i];
    }
    if (tid == 1023) indptr[n] = part[1023];
}
__global__ void k_scatter(const int* __restrict__ dst, int E, int* wp, int* order) {
    int i = blockIdx.x * blockDim.x + threadIdx.x;
    if (i < E) {
        int p = atomicAdd(&wp[dst[i]], 1);
        order[p] = i;
    }
}
// deterministic: restore ascending edge-id order within each segment
__global__ void k_sortseg(const int* __restrict__ indptr, int nseg, int* order) {
    int j = blockIdx.x * blockDim.x + threadIdx.x;
    if (j >= nseg) return;
    int b = indptr[j], e = indptr[j + 1];
    for (int i = b + 1; i < e; i++) {
        int v = order[i];
        int k = i - 1;
        while (k >= b && order[k] > v) { order[k + 1] = order[k]; k--; }
        order[k + 1] = v;
    }
}

// s[n,h] = sum_d h[n, h*64+d] * att[h*64+d]
__global__ void k_score(const float* __restrict__ h, const float* __restrict__ att,
                        float* __restrict__ s) {
    int r = blockIdx.x;
    int t = threadIdx.x;
    __shared__ float sh[256];
    sh[t] = h[(size_t)r * HID + t] * att[t];
    __syncthreads();
    for (int off = 32; off >= 1; off >>= 1) {
        if ((t & 63) < off) sh[t] += sh[t + off];
        __syncthreads();
    }
    if ((t & 63) == 0) s[(size_t)r * HEADS + (t >> 6)] = sh[t];
}

__device__ __forceinline__ float lrelu(float x) { return x > 0.f ? x : 0.2f * x; }

// per-segment softmax coefficients: c[e,h] = exp(lg-mx)/(den+1e-16) * vals[e]
__global__ void k_coef(const int* __restrict__ order, const int* __restrict__ indptr,
                       const int* __restrict__ src, const float* __restrict__ vals,
                       const float* __restrict__ s, float* __restrict__ c, int nseg) {
    int w = (blockIdx.x * blockDim.x + threadIdx.x) >> 5;
    int lane = threadIdx.x & 31;
    if (w >= nseg) return;
    int beg = indptr[w], end = indptr[w + 1];
    if (beg == end) return;
    float m0 = -1e30f, m1 = -1e30f, m2 = -1e30f, m3 = -1e30f;
    for (int p = beg + lane; p < end; p += 32) {
        int e = order[p];
        float4 sv = *(const float4*)(s + (size_t)src[e] * 4);
        m0 = fmaxf(m0, lrelu(sv.x)); m1 = fmaxf(m1, lrelu(sv.y));
        m2 = fmaxf(m2, lrelu(sv.z)); m3 = fmaxf(m3, lrelu(sv.w));
    }
    for (int off = 16; off; off >>= 1) {
        m0 = fmaxf(m0, __shfl_xor_sync(0xffffffffu, m0, off));
        m1 = fmaxf(m1, __shfl_xor_sync(0xffffffffu, m1, off));
        m2 = fmaxf(m2, __shfl_xor_sync(0xffffffffu, m2, off));
        m3 = fmaxf(m3, __shfl_xor_sync(0xffffffffu, m3, off));
    }
    float d0 = 0.f, d1 = 0.f, d2 = 0.f, d3 = 0.f;
    for (int p = beg + lane; p < end; p += 32) {
        int e = order[p];
        float4 sv = *(const float4*)(s + (size_t)src[e] * 4);
        d0 += expf(lrelu(sv.x) - m0); d1 += expf(lrelu(sv.y) - m1);
        d2 += expf(lrelu(sv.z) - m2); d3 += expf(lrelu(sv.w) - m3);
    }
    for (int off = 16; off; off >>= 1) {
        d0 += __shfl_xor_sync(0xffffffffu, d0, off);
        d1 += __shfl_xor_sync(0xffffffffu, d1, off);
        d2 += __shfl_xor_sync(0xffffffffu, d2, off);
        d3 += __shfl_xor_sync(0xffffffffu, d3, off);
    }
    float i0 = 1.f / (d0 + 1e-16f), i1 = 1.f / (d1 + 1e-16f);
    float i2 = 1.f / (d2 + 1e-16f), i3 = 1.f / (d3 + 1e-16f);
    for (int p = beg + lane; p < end; p += 32) {
        int e = order[p];
        float4 sv = *(const float4*)(s + (size_t)src[e] * 4);
        float v = vals[e];
        float4 cc;
        cc.x = expf(lrelu(sv.x) - m0) * i0 * v;
        cc.y = expf(lrelu(sv.y) - m1) * i1 * v;
        cc.z = expf(lrelu(sv.z) - m2) * i2 * v;
        cc.w = expf(lrelu(sv.w) - m3) * i3 * v;
        *(float4*)(c + (size_t)e * 4) = cc;
    }
}

// out[j, t] = sum_edges c[e, t/64] * h[src[e], t] + bias[t]
__global__ void k_reduce(const int* __restrict__ order, const int* __restrict__ indptr,
                         const int* __restrict__ src, const float* __restrict__ c,
                         const float* __restrict__ h, const float* __restrict__ bias,
                         float* __restrict__ out) {
    int j = blockIdx.x;
    int t = threadIdx.x;
    int head = t >> 6;
    __shared__ int ssrc[64];
    __shared__ float scoef[64 * 4];
    int beg = indptr[j], end = indptr[j + 1];
    float acc = 0.f;
    for (int ch = beg; ch < end; ch += 64) {
        int n = min(64, end - ch);
        if (t < n) {
            int e = order[ch + t];
            ssrc[t] = src[e];
            *(float4*)&scoef[t * 4] = *(const float4*)(c + (size_t)e * 4);
        }
        __syncthreads();
        for (int q = 0; q < n; q++)
            acc += scoef[q * 4 + head] * h[(size_t)ssrc[q] * HID + t];
        __syncthreads();
    }
    out[(size_t)j * HID + t] = acc + bias[t];
}

// ---------------- tiled SGEMM: C[M,N] = (gather(A)+abias) @ B + cbias ----------
// BM=128 BN=128 BK=8, 256 threads, 8x8 microtile. Requires M%128==0, N%128==0, K%8==0.
__global__ __launch_bounds__(256) void k_sgemm(
    const float* __restrict__ A, const int* __restrict__ gidx,
    const float* __restrict__ abias, const float* __restrict__ B,
    const float* __restrict__ cbias, float* __restrict__ C,
    int M, int N, int K) {
    __shared__ float As[8][128];
    __shared__ float Bs[8][128];
    int tid = threadIdx.x;
    int bm = blockIdx.y * 128;
    int bn = blockIdx.x * 128;
    int lrow = tid >> 1;
    int lk = (tid & 1) * 4;
    int bk = tid >> 5;
    int bcol = (tid & 31) * 4;
    int tx = tid & 15, ty = tid >> 4;
    int arow = bm + lrow;
    size_t abase = (size_t)(gidx ? gidx[arow] : arow) * K;
    float acc[8][8];
#pragma unroll
    for (int i = 0; i < 8; i++)
#pragma unroll
        for (int j = 0; j < 8; j++) acc[i][j] = 0.f;

    for (int k0 = 0; k0 < K; k0 += 8) {
        float4 av = *(const float4*)(A + abase + k0 + lk);
        if (abias) {
            float4 ab = *(const float4*)(abias + k0 + lk);
            av.x += ab.x; av.y += ab.y; av.z += ab.z; av.w += ab.w;
        }
        As[lk + 0][lrow] = av.x; As[lk + 1][lrow] = av.y;
        As[lk + 2][lrow] = av.z; As[lk + 3][lrow] = av.w;
        float4 bv = *(const float4*)(B + (size_t)(k0 + bk) * N + bn + bcol);
        *(float4*)&Bs[bk][bcol] = bv;
        __syncthreads();
#pragma unroll
        for (int kk = 0; kk < 8; kk++) {
            float4 a0 = *(float4*)&As[kk][ty * 8];
            float4 a1 = *(float4*)&As[kk][ty * 8 + 4];
            float4 b0 = *(float4*)&Bs[kk][tx * 8];
            float4 b1 = *(float4*)&Bs[kk][tx * 8 + 4];
            float ar[8] = {a0.x, a0.y, a0.z, a0.w, a1.x, a1.y, a1.z, a1.w};
            float br[8] = {b0.x, b0.y, b0.z, b0.w, b1.x, b1.y, b1.z, b1.w};
#pragma unroll
            for (int i = 0; i < 8; i++)
#pragma unroll
                for (int j = 0; j < 8; j++) acc[i][j] += ar[i] * br[j];
        }
        __syncthreads();
    }
#pragma unroll
    for (int i = 0; i < 8; i++) {
        size_t r = (size_t)(bm + ty * 8 + i) * N + bn + tx * 8;
#pragma unroll
        for (int j = 0; j < 8; j += 4) {
            float4 v;
            v.x = acc[i][j]; v.y = acc[i][j + 1]; v.z = acc[i][j + 2]; v.w = acc[i][j + 3];
            if (cbias) {
                float4 cb = *(const float4*)(cbias + bn + tx * 8 + j);
                v.x += cb.x; v.y += cb.y; v.z += cb.z; v.w += cb.w;
            }
            *(float4*)(C + r + j) = v;
        }
    }
}

// ---------------- bf16 split for error-compensated tensor-core dot ----------
__global__ void k_split(const float* __restrict__ x, __nv_bfloat16* __restrict__ hi,
                        __nv_bfloat16* __restrict__ lo, int n) {
    int i = blockIdx.x * blockDim.x + threadIdx.x;
    if (i < n) {
        float v = x[i];
        __nv_bfloat16 h = __float2bfloat16(v);
        hi[i] = h;
        lo[i] = __float2bfloat16(v - __bfloat162float(h));
    }
}

// ---------------- NT GEMM via bf16x3 mma: C[8192,8192] = E @ E^T, K=512 --------
#define DSTRIDE 24  // smem row stride (bf16 elems): conflict-free for ldmatrix

#define LDSM4(R, ADDR)                                                        \
    asm volatile("ldmatrix.sync.aligned.m8n8.x4.shared.b16 {%0,%1,%2,%3}, [%4];" \
                 : "=r"((R)[0]), "=r"((R)[1]), "=r"((R)[2]), "=r"((R)[3])     \
                 : "r"(ADDR))

#define MMA16816(C, A, B0, B1)                                                \
    asm volatile(                                                             \
        "mma.sync.aligned.m16n8k16.row.col.f32.bf16.bf16.f32 "                \
        "{%0,%1,%2,%3},{%4,%5,%6,%7},{%8,%9},{%0,%1,%2,%3};"                  \
        : "+f"((C)[0]), "+f"((C)[1]), "+f"((C)[2]), "+f"((C)[3])              \
        : "r"((A)[0]), "r"((A)[1]), "r"((A)[2]), "r"((A)[3]), "r"(B0), "r"(B1))

__global__ __launch_bounds__(512) void k_dot_mma(
    const __nv_bfloat16* __restrict__ Ehi, const __nv_bfloat16* __restrict__ Elo,
    float* __restrict__ C) {
    __shared__ __nv_bfloat16 sA[2][2][128 * DSTRIDE];  // [stage][hi/lo]
    __shared__ __nv_bfloat16 sB[2][2][128 * DSTRIDE];
    int tid = threadIdx.x;
    int lane = tid & 31, wid = tid >> 5;
    int wm = wid >> 2, wn = wid & 3;  // 4x4 warps, 32x32 tile each
    int bi = blockIdx.y * 128, bj = blockIdx.x * 128;

    // global load: each thread loads 4 bf16 (uint2) per array per k-step
    int grow = tid >> 2;
    int gcol = (tid & 3) * 4;
    const __nv_bfloat16* pAhi = Ehi + (size_t)(bi + grow) * EMBD + gcol;
    const __nv_bfloat16* pAlo = Elo + (size_t)(bi + grow) * EMBD + gcol;
    const __nv_bfloat16* pBhi = Ehi + (size_t)(bj + grow) * EMBD + gcol;
    const __nv_bfloat16* pBlo = Elo + (size_t)(bj + grow) * EMBD + gcol;
    int soff = grow * DSTRIDE + gcol;

    // ldmatrix lane addressing
    int lrow = (lane & 7) + ((lane >> 3) & 1) * 8;
    int lcol = (lane >> 4) * 8;

    float acc[2][4][4];
#pragma unroll
    for (int m = 0; m < 2; m++)
#pragma unroll
        for (int n = 0; n < 4; n++)
#pragma unroll
            for (int q = 0; q < 4; q++) acc[m][n][q] = 0.f;

    // prologue: tile 0 -> smem[0], tile 1 -> regs
    uint2 vah = *(const uint2*)pAhi;
    uint2 val = *(const uint2*)pAlo;
    uint2 vbh = *(const uint2*)pBhi;
    uint2 vbl = *(const uint2*)pBlo;
    *(uint2*)&sA[0][0][soff] = vah;
    *(uint2*)&sA[0][1][soff] = val;
    *(uint2*)&sB[0][0][soff] = vbh;
    *(uint2*)&sB[0][1][soff] = vbl;
    vah = *(const uint2*)(pAhi + 16);
    val = *(const uint2*)(pAlo + 16);
    vbh = *(const uint2*)(pBhi + 16);
    vbl = *(const uint2*)(pBlo + 16);
    __syncthreads();

    for (int it = 0; it < EMBD / 16; it++) {
        int st = it & 1;
        uint32_t fa[2][2][4], fb[2][2][4];
#pragma unroll
        for (int mt = 0; mt < 2; mt++)
#pragma unroll
            for (int op = 0; op < 2; op++) {
                uint32_t ad = (uint32_t)__cvta_generic_to_shared(
                    &sA[st][op][(wm * 32 + mt * 16 + lrow) * DSTRIDE + lcol]);
                LDSM4(fa[mt][op], ad);
            }
#pragma unroll
        for (int np = 0; np < 2; np++)
#pragma unroll
            for (int op = 0; op < 2; op++) {
                uint32_t ad = (uint32_t)__cvta_generic_to_shared(
                    &sB[st][op][(wn * 32 + np * 16 + lrow) * DSTRIDE + lcol]);
                LDSM4(fb[np][op], ad);
            }
        if (it < EMBD / 16 - 1) {
            int ns = st ^ 1;
            *(uint2*)&sA[ns][0][soff] = vah;
            *(uint2*)&sA[ns][1][soff] = val;
            *(uint2*)&sB[ns][0][soff] = vbh;
            *(uint2*)&sB[ns][1][soff] = vbl;
        }
        __syncthreads();
        if (it < EMBD / 16 - 2) {
            vah = *(const uint2*)(pAhi + (it + 2) * 16);
            val = *(const uint2*)(pAlo + (it + 2) * 16);
            vbh = *(const uint2*)(pBhi + (it + 2) * 16);
            vbl = *(const uint2*)(pBlo + (it + 2) * 16);
        }
#pragma unroll
        for (int mt = 0; mt < 2; mt++)
#pragma unroll
            for (int np = 0; np < 2; np++)
#pragma unroll
                for (int s = 0; s < 2; s++) {
                    int nt = np * 2 + s;
                    // hi*hi + hi*lo + lo*hi
                    MMA16816(acc[mt][nt], fa[mt][0], fb[np][0][s], fb[np][0][2 + s]);
                    MMA16816(acc[mt][nt], fa[mt][0], fb[np][1][s], fb[np][1][2 + s]);
                    MMA16816(acc[mt][nt], fa[mt][1], fb[np][0][s], fb[np][0][2 + s]);
                }
    }

    // epilogue
#pragma unroll
    for (int mt = 0; mt < 2; mt++) {
        int r0 = bi + wm * 32 + mt * 16 + (lane >> 2);
#pragma unroll
        for (int nt = 0; nt < 4; nt++) {
            int cc = bj + wn * 32 + nt * 8 + (lane & 3) * 2;
            float2 v0 = {acc[mt][nt][0], acc[mt][nt][1]};
            float2 v1 = {acc[mt][nt][2], acc[mt][nt][3]};
            *(float2*)(C + (size_t)r0 * BB + cc) = v0;
            *(float2*)(C + (size_t)(r0 + 8) * BB + cc) = v1;
        }
    }
}

// skip connection + interpolation accumulate
__global__ void k_accum(const float* __restrict__ out0, const int* __restrict__ res,
                        const float* __restrict__ gat1, const float* __restrict__ masks,
                        const float* __restrict__ iw, int mod, float* __restrict__ acc) {
    int b = blockIdx.x;
    int t = threadIdx.x;
    __shared__ float coef;
    __shared__ int rid;
    if (t == 0) {
        float w0 = iw[0], w1 = iw[1], w2 = iw[2];
        float mw = fmaxf(w0, fmaxf(w1, w2));
        float e0 = expf(w0 - mw), e1 = expf(w1 - mw), e2 = expf(w2 - mw);
        float ws = e0 + e1 + e2;
        float wi = (mod == 0 ? e0 : (mod == 1 ? e1 : e2)) / ws;
        float m0 = masks[b * 3 + 0], m1 = masks[b * 3 + 1], m2 = masks[b * 3 + 2];
        float msum = m0 + m1 + m2;
        float r = 1.0f + 1.0f / powf(1.0f + 3.0f, 20.0f) + 1.0f / powf(msum, 20.0f);
        r = floorf(r);
        r = r / (r + 1e-10f);
        float z0 = m0 * r, z1 = m1 * r, z2 = m2 * r;
        z0 = z0 + (1.0f - z0) * (-1e10f);
        z1 = z1 + (1.0f - z1) * (-1e10f);
        z2 = z2 + (1.0f - z2) * (-1e10f);
        float zm = fmaxf(z0, fmaxf(z1, z2));
        float x0 = expf(z0 - zm), x1 = expf(z1 - zm), x2 = expf(z2 - zm);
        float xs = x0 + x1 + x2;
        float im = (mod == 0 ? x0 : (mod == 1 ? x1 : x2)) / xs;
        coef = wi * im;
        rid = res[b];
    }
    __syncthreads();
    acc[(size_t)b * HID + t] += coef * (out0[(size_t)rid * HID + t] + gat1[(size_t)b * HID + t]);
}

__global__ void k_weights(const float* __restrict__ iw, float* __restrict__ o) {
    float w0 = iw[0], w1 = iw[1], w2 = iw[2];
    float m = fmaxf(w0, fmaxf(w1, w2));
    float e0 = expf(w0 - m), e1 = expf(w1 - m), e2 = expf(w2 - m);
    float s = e0 + e1 + e2;
    o[0] = e0 / s; o[1] = e1 / s; o[2] = e2 / s;
}

// ---------------- host side ----------------
static void build_csr(const int* dst, int E, int nseg,
                      int* cnt, int* indptr, int* wp, int* order) {
    k_zero_i<<<(nseg + 255) / 256, 256>>>(cnt, nseg);
    k_hist<<<(E + 255) / 256, 256>>>(dst, E, cnt);
    k_scan<<<1, 1024>>>(cnt, nseg, indptr, wp);
    k_scatter<<<(E + 255) / 256, 256>>>(dst, E, wp, order);
    k_sortseg<<<(nseg + 255) / 256, 256>>>(indptr, nseg, order);
}

extern "C" void kernel_launch(void* const* d_in, const int* in_sizes, int n_in,
                              void* d_out, int out_size) {
    const int*   n_id     = (const int*)d_in[0];
    const int*   src0     = (const int*)d_in[1];
    const int*   dst0     = (const int*)d_in[2];
    const int*   src1     = (const int*)d_in[3];
    const int*   dst1     = (const int*)d_in[4];
    const int*   res_n_id = (const int*)d_in[5];
    const float* vals0    = (const float*)d_in[6];
    const float* vals1    = (const float*)d_in[7];
    const float* masks    = (const float*)d_in[8];
    const float* pre_W    = (const float*)d_in[9];
    const float* pre_b    = (const float*)d_in[10];
    const float* W_gat    = (const float*)d_in[11];
    const float* att      = (const float*)d_in[12];
    const float* gat_b    = (const float*)d_in[13];
    const float* interp_w = (const float*)d_in[14];
    const float* emb_W    = (const float*)d_in[15];
    const float* emb_b    = (const float*)d_in[16];

    float* dot = (float*)d_out;
    float* emb = dot + (size_t)BB * BB;
    float* wout = emb + (size_t)BB * EMBD;

    float *h, *s, *out0, *gat1, *acc, *c;
    int *cnt, *indptr, *wp, *order;
    __nv_bfloat16 *ehi, *elo;
    cudaGetSymbolAddress((void**)&h, g_h);
    cudaGetSymbolAddress((void**)&s, g_s);
    cudaGetSymbolAddress((void**)&out0, g_out0);
    cudaGetSymbolAddress((void**)&gat1, g_gat1);
    cudaGetSymbolAddress((void**)&acc, g_acc);
    cudaGetSymbolAddress((void**)&c, g_c);
    cudaGetSymbolAddress((void**)&cnt, g_cnt);
    cudaGetSymbolAddress((void**)&indptr, g_indptr);
    cudaGetSymbolAddress((void**)&wp, g_wp);
    cudaGetSymbolAddress((void**)&order, g_order);
    cudaGetSymbolAddress((void**)&ehi, g_ehi);
    cudaGetSymbolAddress((void**)&elo, g_elo);

    k_zero_f<<<(BB * HID + 255) / 256, 256>>>(acc, BB * HID);

    const int IN_SZ = 50000;
    for (int i = 0; i < MODS; i++) {
        const float* Wg  = W_gat + (size_t)i * HID * HID;
        const float* ai  = att + (size_t)i * HID;
        const float* gbi = gat_b + (size_t)i * HID;

        // ---- block 0: N0 sources -> N1 targets ----
        const int* s0 = src0 + (size_t)i * EE0;
        build_csr(dst0 + (size_t)i * EE0, EE0, NN1, cnt, indptr, wp, order);
        {   // h0 = (pre_W[i][n_id] + pre_b[i]) @ Wg
            dim3 grid(HID / 128, NN0 / 128);
            k_sgemm<<<grid, 256>>>(pre_W + (size_t)i * IN_SZ * HID,
                                   n_id + (size_t)i * NN0,
                                   pre_b + (size_t)i * HID,
                                   Wg, nullptr, h, NN0, HID, HID);
        }
        k_score<<<NN0, 256>>>(h, ai, s);
        k_coef<<<(NN1 * 32 + 255) / 256, 256>>>(order, indptr, s0,
                                                vals0 + (size_t)i * EE0, s, c, NN1);
        k_reduce<<<NN1, 256>>>(order, indptr, s0, c, h, gbi, out0);

        // ---- block 1: N1 sources -> B targets ----
        const int* s1 = src1 + (size_t)i * EE1;
        build_csr(dst1 + (size_t)i * EE1, EE1, BB, cnt, indptr, wp, order);
        {   // h1 = out0 @ Wg
            dim3 grid(HID / 128, NN1 / 128);
            k_sgemm<<<grid, 256>>>(out0, nullptr, nullptr, Wg, nullptr, h,
                                   NN1, HID, HID);
        }
        k_score<<<NN1, 256>>>(h, ai, s);
        k_coef<<<(BB * 32 + 255) / 256, 256>>>(order, indptr, s1,
                                               vals1 + (size_t)i * EE1, s, c, BB);
        k_reduce<<<BB, 256>>>(order, indptr, s1, c, h, gbi, gat1);

        // ---- skip + interpolation accumulate ----
        k_accum<<<BB, 256>>>(out0, res_n_id + (size_t)i * BB, gat1, masks,
                             interp_w, i, acc);
    }

    // emb = acc @ emb_W + emb_b
    {
        dim3 grid(EMBD / 128, BB / 128);
        k_sgemm<<<grid, 256>>>(acc, nullptr, nullptr, emb_W, emb_b, emb,
                               BB, EMBD, HID);
    }
    // dot = emb @ emb^T via bf16x3 tensor-core emulation
    k_split<<<(BB * EMBD + 255) / 256, 256>>>(emb, ehi, elo, BB * EMBD);
    {
        dim3 grid(BB / 128, BB / 128);
        k_dot_mma<<<grid, 512>>>(ehi, elo, dot);
    }
    k_weights<<<1, 1>>>(interp_w, wout);
}

// round 4
// speedup vs baseline: 1.7460x; 1.2901x over previous
#include <cuda_runtime.h>
#include <cuda_bf16.h>
#include <cstdint>
#include <math.h>

#define MODS 3
#define HEADS 4
#define HID 256
#define EMBD 512
#define NN0 49152
#define NN1 16384
#define BB 8192
#define EE0 262144
#define EE1 131072

#define TSEG (MODS * (NN1 + BB))   // 73728 total segments across 6 graphs
#define TEDG (MODS * (EE0 + EE1))  // 1179648 total edges

// ---------------- static scratch (allowed: __device__ globals) ----------------
__device__ float g_h[(size_t)NN0 * HID];      // h0 (reused as h1)
__device__ float g_s[(size_t)NN0 * HEADS];    // attention scores per source node
__device__ float g_out0[(size_t)NN1 * HID];   // block-0 GAT output
__device__ float g_gat1[(size_t)BB * HID];    // block-1 GAT output
__device__ float g_acc[(size_t)BB * HID];     // accumulated across modalities
__device__ float g_c[(size_t)EE0 * HEADS];    // per-edge coefficients alpha*val
__device__ int   g_cnt[TSEG];
__device__ int   g_indptr[TSEG + 1];
__device__ int   g_wp[TSEG];
__device__ int   g_order[TEDG];
__device__ __nv_bfloat16 g_ehi[(size_t)BB * EMBD];
__device__ __nv_bfloat16 g_elo[(size_t)BB * EMBD];

// ---------------- small utility kernels ----------------
__global__ void k_zero_f(float* p, int n) {
    int i = blockIdx.x * blockDim.x + threadIdx.x;
    if (i < n) p[i] = 0.f;
}
__global__ void k_zero_i(int* p, int n) {
    int i = blockIdx.x * blockDim.x + threadIdx.x;
    if (i < n) p[i] = 0;
}

// batched histogram over all 6 graphs (3 mods x {block0, block1})
__global__ void k_hist_all(const int* __restrict__ dst0, const int* __restrict__ dst1,
                           int* cnt) {
    int i = blockIdx.x * blockDim.x + threadIdx.x;
    if (i >= TEDG) return;
    int mod = i / (EE0 + EE1);
    int rem = i - mod * (EE0 + EE1);
    int seg;
    if (rem < EE0) {
        seg = mod * (NN1 + BB) + dst0[(size_t)mod * EE0 + rem];
    } else {
        seg = mod * (NN1 + BB) + NN1 + dst1[(size_t)mod * EE1 + (rem - EE0)];
    }
    atomicAdd(&cnt[seg], 1);
}

// single-block exclusive scan (n <= ~128k), writes indptr[0..n] and wp=indptr
__global__ void k_scan(const int* __restrict__ cnt, int n, int* indptr, int* wp) {
    __shared__ int part[1024];
    int tid = threadIdx.x;
    int per = (n + 1023) / 1024;
    int beg = tid * per;
    int end = min(beg + per, n);
    int sum = 0;
    for (int i = beg; i < end; i++) sum += cnt[i];
    part[tid] = sum;
    __syncthreads();
    for (int off = 1; off < 1024; off <<= 1) {
        int v = (tid >= off) ? part[tid - off] : 0;
        __syncthreads();
        part[tid] += v;
        __syncthreads();
    }
    int run = part[tid] - sum;  // exclusive prefix
    for (int i = beg; i < end; i++) {
        indptr[i] = run;
        wp[i] = run;
        run += cnt[i];
    }
    if (tid == 1023) indptr[n] = part[1023];
}

// batched scatter: order[] holds LOCAL edge index within its graph
__global__ void k_scatter_all(const int* __restrict__ dst0, const int* __restrict__ dst1,
                              int* wp, int* order) {
    int i = blockIdx.x * blockDim.x + threadIdx.x;
    if (i >= TEDG) return;
    int mod = i / (EE0 + EE1);
    int rem = i - mod * (EE0 + EE1);
    int seg, loc;
    if (rem < EE0) {
        loc = rem;
        seg = mod * (NN1 + BB) + dst0[(size_t)mod * EE0 + rem];
    } else {
        loc = rem - EE0;
        seg = mod * (NN1 + BB) + NN1 + dst1[(size_t)mod * EE1 + loc];
    }
    int p = atomicAdd(&wp[seg], 1);
    order[p] = loc;
}

// deterministic: restore ascending edge-id order within each segment
__global__ void k_sortseg(const int* __restrict__ indptr, int nseg, int* order) {
    int j = blockIdx.x * blockDim.x + threadIdx.x;
    if (j >= nseg) return;
    int b = indptr[j], e = indptr[j + 1];
    for (int i = b + 1; i < e; i++) {
        int v = order[i];
        int k = i - 1;
        while (k >= b && order[k] > v) { order[k + 1] = order[k]; k--; }
        order[k + 1] = v;
    }
}

// s[n,h] = sum_d h[n, h*64+d] * att[h*64+d]
__global__ void k_score(const float* __restrict__ h, const float* __restrict__ att,
                        float* __restrict__ s) {
    int r = blockIdx.x;
    int t = threadIdx.x;
    __shared__ float sh[256];
    sh[t] = h[(size_t)r * HID + t] * att[t];
    __syncthreads();
    for (int off = 32; off >= 1; off >>= 1) {
        if ((t & 63) < off) sh[t] += sh[t + off];
        __syncthreads();
    }
    if ((t & 63) == 0) s[(size_t)r * HEADS + (t >> 6)] = sh[t];
}

__device__ __forceinline__ float lrelu(float x) { return x > 0.f ? x : 0.2f * x; }

// per-segment softmax coefficients: c[e,h] = exp(lg-mx)/(den+1e-16) * vals[e]
__global__ void k_coef(const int* __restrict__ order, const int* __restrict__ indptr,
                       const int* __restrict__ src, const float* __restrict__ vals,
                       const float* __restrict__ s, float* __restrict__ c, int nseg) {
    int w = (blockIdx.x * blockDim.x + threadIdx.x) >> 5;
    int lane = threadIdx.x & 31;
    if (w >= nseg) return;
    int beg = indptr[w], end = indptr[w + 1];
    if (beg == end) return;
    float m0 = -1e30f, m1 = -1e30f, m2 = -1e30f, m3 = -1e30f;
    for (int p = beg + lane; p < end; p += 32) {
        int e = order[p];
        float4 sv = *(const float4*)(s + (size_t)src[e] * 4);
        m0 = fmaxf(m0, lrelu(sv.x)); m1 = fmaxf(m1, lrelu(sv.y));
        m2 = fmaxf(m2, lrelu(sv.z)); m3 = fmaxf(m3, lrelu(sv.w));
    }
    for (int off = 16; off; off >>= 1) {
        m0 = fmaxf(m0, __shfl_xor_sync(0xffffffffu, m0, off));
        m1 = fmaxf(m1, __shfl_xor_sync(0xffffffffu, m1, off));
        m2 = fmaxf(m2, __shfl_xor_sync(0xffffffffu, m2, off));
        m3 = fmaxf(m3, __shfl_xor_sync(0xffffffffu, m3, off));
    }
    float d0 = 0.f, d1 = 0.f, d2 = 0.f, d3 = 0.f;
    for (int p = beg + lane; p < end; p += 32) {
        int e = order[p];
        float4 sv = *(const float4*)(s + (size_t)src[e] * 4);
        d0 += expf(lrelu(sv.x) - m0); d1 += expf(lrelu(sv.y) - m1);
        d2 += expf(lrelu(sv.z) - m2); d3 += expf(lrelu(sv.w) - m3);
    }
    for (int off = 16; off; off >>= 1) {
        d0 += __shfl_xor_sync(0xffffffffu, d0, off);
        d1 += __shfl_xor_sync(0xffffffffu, d1, off);
        d2 += __shfl_xor_sync(0xffffffffu, d2, off);
        d3 += __shfl_xor_sync(0xffffffffu, d3, off);
    }
    float i0 = 1.f / (d0 + 1e-16f), i1 = 1.f / (d1 + 1e-16f);
    float i2 = 1.f / (d2 + 1e-16f), i3 = 1.f / (d3 + 1e-16f);
    for (int p = beg + lane; p < end; p += 32) {
        int e = order[p];
        float4 sv = *(const float4*)(s + (size_t)src[e] * 4);
        float v = vals[e];
        float4 cc;
        cc.x = expf(lrelu(sv.x) - m0) * i0 * v;
        cc.y = expf(lrelu(sv.y) - m1) * i1 * v;
        cc.z = expf(lrelu(sv.z) - m2) * i2 * v;
        cc.w = expf(lrelu(sv.w) - m3) * i3 * v;
        *(float4*)(c + (size_t)e * 4) = cc;
    }
}

// out[j, t] = sum_edges c[e, t/64] * h[src[e], t] + bias[t]
__global__ void k_reduce(const int* __restrict__ order, const int* __restrict__ indptr,
                         const int* __restrict__ src, const float* __restrict__ c,
                         const float* __restrict__ h, const float* __restrict__ bias,
                         float* __restrict__ out) {
    int j = blockIdx.x;
    int t = threadIdx.x;
    int head = t >> 6;
    __shared__ int ssrc[64];
    __shared__ float scoef[64 * 4];
    int beg = indptr[j], end = indptr[j + 1];
    float acc = 0.f;
    for (int ch = beg; ch < end; ch += 64) {
        int n = min(64, end - ch);
        if (t < n) {
            int e = order[ch + t];
            ssrc[t] = src[e];
            *(float4*)&scoef[t * 4] = *(const float4*)(c + (size_t)e * 4);
        }
        __syncthreads();
        for (int q = 0; q < n; q++)
            acc += scoef[q * 4 + head] * h[(size_t)ssrc[q] * HID + t];
        __syncthreads();
    }
    out[(size_t)j * HID + t] = acc + bias[t];
}

// ---------------- tiled SGEMM: C[M,N] = (gather(A)+abias) @ B + cbias ----------
// Optionally also writes bf16 hi/lo split of the output (for the dot GEMM input).
__global__ __launch_bounds__(256) void k_sgemm(
    const float* __restrict__ A, const int* __restrict__ gidx,
    const float* __restrict__ abias, const float* __restrict__ B,
    const float* __restrict__ cbias, float* __restrict__ C,
    int M, int N, int K,
    __nv_bfloat16* __restrict__ ohi, __nv_bfloat16* __restrict__ olo) {
    __shared__ float As[8][128];
    __shared__ float Bs[8][128];
    int tid = threadIdx.x;
    int bm = blockIdx.y * 128;
    int bn = blockIdx.x * 128;
    int lrow = tid >> 1;
    int lk = (tid & 1) * 4;
    int bk = tid >> 5;
    int bcol = (tid & 31) * 4;
    int tx = tid & 15, ty = tid >> 4;
    int arow = bm + lrow;
    size_t abase = (size_t)(gidx ? gidx[arow] : arow) * K;
    float acc[8][8];
#pragma unroll
    for (int i = 0; i < 8; i++)
#pragma unroll
        for (int j = 0; j < 8; j++) acc[i][j] = 0.f;

    for (int k0 = 0; k0 < K; k0 += 8) {
        float4 av = *(const float4*)(A + abase + k0 + lk);
        if (abias) {
            float4 ab = *(const float4*)(abias + k0 + lk);
            av.x += ab.x; av.y += ab.y; av.z += ab.z; av.w += ab.w;
        }
        As[lk + 0][lrow] = av.x; As[lk + 1][lrow] = av.y;
        As[lk + 2][lrow] = av.z; As[lk + 3][lrow] = av.w;
        float4 bv = *(const float4*)(B + (size_t)(k0 + bk) * N + bn + bcol);
        *(float4*)&Bs[bk][bcol] = bv;
        __syncthreads();
#pragma unroll
        for (int kk = 0; kk < 8; kk++) {
            float4 a0 = *(float4*)&As[kk][ty * 8];
            float4 a1 = *(float4*)&As[kk][ty * 8 + 4];
            float4 b0 = *(float4*)&Bs[kk][tx * 8];
            float4 b1 = *(float4*)&Bs[kk][tx * 8 + 4];
            float ar[8] = {a0.x, a0.y, a0.z, a0.w, a1.x, a1.y, a1.z, a1.w};
            float br[8] = {b0.x, b0.y, b0.z, b0.w, b1.x, b1.y, b1.z, b1.w};
#pragma unroll
            for (int i = 0; i < 8; i++)
#pragma unroll
                for (int j = 0; j < 8; j++) acc[i][j] += ar[i] * br[j];
        }
        __syncthreads();
    }
#pragma unroll
    for (int i = 0; i < 8; i++) {
        size_t r = (size_t)(bm + ty * 8 + i) * N + bn + tx * 8;
#pragma unroll
        for (int j = 0; j < 8; j += 4) {
            float4 v;
            v.x = acc[i][j]; v.y = acc[i][j + 1]; v.z = acc[i][j + 2]; v.w = acc[i][j + 3];
            if (cbias) {
                float4 cb = *(const float4*)(cbias + bn + tx * 8 + j);
                v.x += cb.x; v.y += cb.y; v.z += cb.z; v.w += cb.w;
            }
            *(float4*)(C + r + j) = v;
            if (ohi) {
                __nv_bfloat16 h0 = __float2bfloat16(v.x), h1 = __float2bfloat16(v.y);
                __nv_bfloat16 h2 = __float2bfloat16(v.z), h3 = __float2bfloat16(v.w);
                __nv_bfloat162* ph = (__nv_bfloat162*)(ohi + r + j);
                ph[0] = __nv_bfloat162(h0, h1);
                ph[1] = __nv_bfloat162(h2, h3);
                __nv_bfloat162* pl = (__nv_bfloat162*)(olo + r + j);
                pl[0] = __nv_bfloat162(__float2bfloat16(v.x - __bfloat162float(h0)),
                                       __float2bfloat16(v.y - __bfloat162float(h1)));
                pl[1] = __nv_bfloat162(__float2bfloat16(v.z - __bfloat162float(h2)),
                                       __float2bfloat16(v.w - __bfloat162float(h3)));
            }
        }
    }
}

// ---------------- NT GEMM via bf16x3 mma, symmetric: C = E @ E^T, K=512 --------
// Triangular grid: only block-pairs (bi >= bj); off-diagonal tiles mirrored.
#define DSTRIDE 24  // smem row stride (bf16 elems): conflict-free for ldmatrix

#define LDSM4(R, ADDR)                                                        \
    asm volatile("ldmatrix.sync.aligned.m8n8.x4.shared.b16 {%0,%1,%2,%3}, [%4];" \
                 : "=r"((R)[0]), "=r"((R)[1]), "=r"((R)[2]), "=r"((R)[3])     \
                 : "r"(ADDR))

#define MMA16816(C, A, B0, B1)                                                \
    asm volatile(                                                             \
        "mma.sync.aligned.m16n8k16.row.col.f32.bf16.bf16.f32 "                \
        "{%0,%1,%2,%3},{%4,%5,%6,%7},{%8,%9},{%0,%1,%2,%3};"                  \
        : "+f"((C)[0]), "+f"((C)[1]), "+f"((C)[2]), "+f"((C)[3])              \
        : "r"((A)[0]), "r"((A)[1]), "r"((A)[2]), "r"((A)[3]), "r"(B0), "r"(B1))

__global__ __launch_bounds__(512) void k_dot_mma(
    const __nv_bfloat16* __restrict__ Ehi, const __nv_bfloat16* __restrict__ Elo,
    float* __restrict__ C) {
    __shared__ __nv_bfloat16 sA[2][2][128 * DSTRIDE];  // [stage][hi/lo]
    __shared__ __nv_bfloat16 sB[2][2][128 * DSTRIDE];
    int tid = threadIdx.x;
    int lane = tid & 31, wid = tid >> 5;
    int wm = wid >> 2, wn = wid & 3;  // 4x4 warps, 32x32 tile each

    // triangular block decode: blockIdx.x in [0, 64*65/2)
    int bid = blockIdx.x;
    int brow = (int)((sqrtf(8.0f * (float)bid + 1.0f) - 1.0f) * 0.5f);
    while ((brow + 1) * (brow + 2) / 2 <= bid) brow++;
    while (brow * (brow + 1) / 2 > bid) brow--;
    int bcol = bid - brow * (brow + 1) / 2;
    int bi = brow * 128, bj = bcol * 128;  // bi >= bj

    // global load: each thread loads 4 bf16 (uint2) per array per k-step
    int grow = tid >> 2;
    int gcol = (tid & 3) * 4;
    const __nv_bfloat16* pAhi = Ehi + (size_t)(bi + grow) * EMBD + gcol;
    const __nv_bfloat16* pAlo = Elo + (size_t)(bi + grow) * EMBD + gcol;
    const __nv_bfloat16* pBhi = Ehi + (size_t)(bj + grow) * EMBD + gcol;
    const __nv_bfloat16* pBlo = Elo + (size_t)(bj + grow) * EMBD + gcol;
    int soff = grow * DSTRIDE + gcol;

    // ldmatrix lane addressing
    int lrow = (lane & 7) + ((lane >> 3) & 1) * 8;
    int lcol = (lane >> 4) * 8;

    float acc[2][4][4];
#pragma unroll
    for (int m = 0; m < 2; m++)
#pragma unroll
        for (int n = 0; n < 4; n++)
#pragma unroll
            for (int q = 0; q < 4; q++) acc[m][n][q] = 0.f;

    // prologue: tile 0 -> smem[0], tile 1 -> regs
    uint2 vah = *(const uint2*)pAhi;
    uint2 val = *(const uint2*)pAlo;
    uint2 vbh = *(const uint2*)pBhi;
    uint2 vbl = *(const uint2*)pBlo;
    *(uint2*)&sA[0][0][soff] = vah;
    *(uint2*)&sA[0][1][soff] = val;
    *(uint2*)&sB[0][0][soff] = vbh;
    *(uint2*)&sB[0][1][soff] = vbl;
    vah = *(const uint2*)(pAhi + 16);
    val = *(const uint2*)(pAlo + 16);
    vbh = *(const uint2*)(pBhi + 16);
    vbl = *(const uint2*)(pBlo + 16);
    __syncthreads();

    for (int it = 0; it < EMBD / 16; it++) {
        int st = it & 1;
        uint32_t fa[2][2][4], fb[2][2][4];
#pragma unroll
        for (int mt = 0; mt < 2; mt++)
#pragma unroll
            for (int op = 0; op < 2; op++) {
                uint32_t ad = (uint32_t)__cvta_generic_to_shared(
                    &sA[st][op][(wm * 32 + mt * 16 + lrow) * DSTRIDE + lcol]);
                LDSM4(fa[mt][op], ad);
            }
#pragma unroll
        for (int np = 0; np < 2; np++)
#pragma unroll
            for (int op = 0; op < 2; op++) {
                uint32_t ad = (uint32_t)__cvta_generic_to_shared(
                    &sB[st][op][(wn * 32 + np * 16 + lrow) * DSTRIDE + lcol]);
                LDSM4(fb[np][op], ad);
            }
        if (it < EMBD / 16 - 1) {
            int ns = st ^ 1;
            *(uint2*)&sA[ns][0][soff] = vah;
            *(uint2*)&sA[ns][1][soff] = val;
            *(uint2*)&sB[ns][0][soff] = vbh;
            *(uint2*)&sB[ns][1][soff] = vbl;
        }
        __syncthreads();
        if (it < EMBD / 16 - 2) {
            vah = *(const uint2*)(pAhi + (it + 2) * 16);
            val = *(const uint2*)(pAlo + (it + 2) * 16);
            vbh = *(const uint2*)(pBhi + (it + 2) * 16);
            vbl = *(const uint2*)(pBlo + (it + 2) * 16);
        }
#pragma unroll
        for (int mt = 0; mt < 2; mt++)
#pragma unroll
            for (int np = 0; np < 2; np++)
#pragma unroll
                for (int s = 0; s < 2; s++) {
                    int nt = np * 2 + s;
                    // hi*hi + hi*lo + lo*hi
                    MMA16816(acc[mt][nt], fa[mt][0], fb[np][0][s], fb[np][0][2 + s]);
                    MMA16816(acc[mt][nt], fa[mt][0], fb[np][1][s], fb[np][1][2 + s]);
                    MMA16816(acc[mt][nt], fa[mt][1], fb[np][0][s], fb[np][0][2 + s]);
                }
    }

    // epilogue: direct tile + mirrored (transposed) tile for off-diagonal blocks
#pragma unroll
    for (int mt = 0; mt < 2; mt++) {
        int r0 = bi + wm * 32 + mt * 16 + (lane >> 2);
#pragma unroll
        for (int nt = 0; nt < 4; nt++) {
            int cc = bj + wn * 32 + nt * 8 + (lane & 3) * 2;
            float2 v0 = {acc[mt][nt][0], acc[mt][nt][1]};
            float2 v1 = {acc[mt][nt][2], acc[mt][nt][3]};
            *(float2*)(C + (size_t)r0 * BB + cc) = v0;
            *(float2*)(C + (size_t)(r0 + 8) * BB + cc) = v1;
            if (bi != bj) {
                C[(size_t)cc * BB + r0] = acc[mt][nt][0];
                C[(size_t)(cc + 1) * BB + r0] = acc[mt][nt][1];
                C[(size_t)cc * BB + r0 + 8] = acc[mt][nt][2];
                C[(size_t)(cc + 1) * BB + r0 + 8] = acc[mt][nt][3];
            }
        }
    }
}

// skip connection + interpolation accumulate
__global__ void k_accum(const float* __restrict__ out0, const int* __restrict__ res,
                        const float* __restrict__ gat1, const float* __restrict__ masks,
                        const float* __restrict__ iw, int mod, float* __restrict__ acc) {
    int b = blockIdx.x;
    int t = threadIdx.x;
    __shared__ float coef;
    __shared__ int rid;
    if (t == 0) {
        float w0 = iw[0], w1 = iw[1], w2 = iw[2];
        float mw = fmaxf(w0, fmaxf(w1, w2));
        float e0 = expf(w0 - mw), e1 = expf(w1 - mw), e2 = expf(w2 - mw);
        float ws = e0 + e1 + e2;
        float wi = (mod == 0 ? e0 : (mod == 1 ? e1 : e2)) / ws;
        float m0 = masks[b * 3 + 0], m1 = masks[b * 3 + 1], m2 = masks[b * 3 + 2];
        float msum = m0 + m1 + m2;
        float r = 1.0f + 1.0f / powf(1.0f + 3.0f, 20.0f) + 1.0f / powf(msum, 20.0f);
        r = floorf(r);
        r = r / (r + 1e-10f);
        float z0 = m0 * r, z1 = m1 * r, z2 = m2 * r;
        z0 = z0 + (1.0f - z0) * (-1e10f);
        z1 = z1 + (1.0f - z1) * (-1e10f);
        z2 = z2 + (1.0f - z2) * (-1e10f);
        float zm = fmaxf(z0, fmaxf(z1, z2));
        float x0 = expf(z0 - zm), x1 = expf(z1 - zm), x2 = expf(z2 - zm);
        float xs = x0 + x1 + x2;
        float im = (mod == 0 ? x0 : (mod == 1 ? x1 : x2)) / xs;
        coef = wi * im;
        rid = res[b];
    }
    __syncthreads();
    acc[(size_t)b * HID + t] += coef * (out0[(size_t)rid * HID + t] + gat1[(size_t)b * HID + t]);
}

__global__ void k_weights(const float* __restrict__ iw, float* __restrict__ o) {
    float w0 = iw[0], w1 = iw[1], w2 = iw[2];
    float m = fmaxf(w0, fmaxf(w1, w2));
    float e0 = expf(w0 - m), e1 = expf(w1 - m), e2 = expf(w2 - m);
    float s = e0 + e1 + e2;
    o[0] = e0 / s; o[1] = e1 / s; o[2] = e2 / s;
}

extern "C" void kernel_launch(void* const* d_in, const int* in_sizes, int n_in,
                              void* d_out, int out_size) {
    const int*   n_id     = (const int*)d_in[0];
    const int*   src0     = (const int*)d_in[1];
    const int*   dst0     = (const int*)d_in[2];
    const int*   src1     = (const int*)d_in[3];
    const int*   dst1     = (const int*)d_in[4];
    const int*   res_n_id = (const int*)d_in[5];
    const float* vals0    = (const float*)d_in[6];
    const float* vals1    = (const float*)d_in[7];
    const float* masks    = (const float*)d_in[8];
    const float* pre_W    = (const float*)d_in[9];
    const float* pre_b    = (const float*)d_in[10];
    const float* W_gat    = (const float*)d_in[11];
    const float* att      = (const float*)d_in[12];
    const float* gat_b    = (const float*)d_in[13];
    const float* interp_w = (const float*)d_in[14];
    const float* emb_W    = (const float*)d_in[15];
    const float* emb_b    = (const float*)d_in[16];

    float* dot = (float*)d_out;
    float* emb = dot + (size_t)BB * BB;
    float* wout = emb + (size_t)BB * EMBD;

    float *h, *s, *out0, *gat1, *acc, *c;
    int *cnt, *indptr, *wp, *order;
    __nv_bfloat16 *ehi, *elo;
    cudaGetSymbolAddress((void**)&h, g_h);
    cudaGetSymbolAddress((void**)&s, g_s);
    cudaGetSymbolAddress((void**)&out0, g_out0);
    cudaGetSymbolAddress((void**)&gat1, g_gat1);
    cudaGetSymbolAddress((void**)&acc, g_acc);
    cudaGetSymbolAddress((void**)&c, g_c);
    cudaGetSymbolAddress((void**)&cnt, g_cnt);
    cudaGetSymbolAddress((void**)&indptr, g_indptr);
    cudaGetSymbolAddress((void**)&wp, g_wp);
    cudaGetSymbolAddress((void**)&order, g_order);
    cudaGetSymbolAddress((void**)&ehi, g_ehi);
    cudaGetSymbolAddress((void**)&elo, g_elo);

    k_zero_f<<<(BB * HID + 255) / 256, 256>>>(acc, BB * HID);

    // ---- batched CSR build for all 6 graphs ----
    k_zero_i<<<(TSEG + 255) / 256, 256>>>(cnt, TSEG);
    k_hist_all<<<(TEDG + 255) / 256, 256>>>(dst0, dst1, cnt);
    k_scan<<<1, 1024>>>(cnt, TSEG, indptr, wp);
    k_scatter_all<<<(TEDG + 255) / 256, 256>>>(dst0, dst1, wp, order);
    k_sortseg<<<(TSEG + 255) / 256, 256>>>(indptr, TSEG, order);

    const int IN_SZ = 50000;
    for (int i = 0; i < MODS; i++) {
        const float* Wg  = W_gat + (size_t)i * HID * HID;
        const float* ai  = att + (size_t)i * HID;
        const float* gbi = gat_b + (size_t)i * HID;
        const int* ip0 = indptr + i * (NN1 + BB);
        const int* ip1 = indptr + i * (NN1 + BB) + NN1;

        // ---- block 0: N0 sources -> N1 targets ----
        const int* s0 = src0 + (size_t)i * EE0;
        {   // h0 = (pre_W[i][n_id] + pre_b[i]) @ Wg
            dim3 grid(HID / 128, NN0 / 128);
            k_sgemm<<<grid, 256>>>(pre_W + (size_t)i * IN_SZ * HID,
                                   n_id + (size_t)i * NN0,
                                   pre_b + (size_t)i * HID,
                                   Wg, nullptr, h, NN0, HID, HID, nullptr, nullptr);
        }
        k_score<<<NN0, 256>>>(h, ai, s);
        k_coef<<<(NN1 * 32 + 255) / 256, 256>>>(order, ip0, s0,
                                                vals0 + (size_t)i * EE0, s, c, NN1);
        k_reduce<<<NN1, 256>>>(order, ip0, s0, c, h, gbi, out0);

        // ---- block 1: N1 sources -> B targets ----
        const int* s1 = src1 + (size_t)i * EE1;
        {   // h1 = out0 @ Wg
            dim3 grid(HID / 128, NN1 / 128);
            k_sgemm<<<grid, 256>>>(out0, nullptr, nullptr, Wg, nullptr, h,
                                   NN1, HID, HID, nullptr, nullptr);
        }
        k_score<<<NN1, 256>>>(h, ai, s);
        k_coef<<<(BB * 32 + 255) / 256, 256>>>(order, ip1, s1,
                                               vals1 + (size_t)i * EE1, s, c, BB);
        k_reduce<<<BB, 256>>>(order, ip1, s1, c, h, gbi, gat1);

        // ---- skip + interpolation accumulate ----
        k_accum<<<BB, 256>>>(out0, res_n_id + (size_t)i * BB, gat1, masks,
                             interp_w, i, acc);
    }

    // emb = acc @ emb_W + emb_b  (+ fused bf16 hi/lo split)
    {
        dim3 grid(EMBD / 128, BB / 128);
        k_sgemm<<<grid, 256>>>(acc, nullptr, nullptr, emb_W, emb_b, emb,
                               BB, EMBD, HID, ehi, elo);
    }
    // dot = emb @ emb^T via bf16x3 tensor-core emulation, symmetric half-grid
    {
        int npairs = (BB / 128) * (BB / 128 + 1) / 2;  // 2080
        k_dot_mma<<<npairs, 512>>>(ehi, elo, dot);
    }
    k_weights<<<1, 1>>>(interp_w, wout);
}

// round 5
// speedup vs baseline: 1.7621x; 1.0092x over previous
#include <cuda_runtime.h>
#include <cuda_bf16.h>
#include <cstdint>
#include <math.h>

#define MODS 3
#define HEADS 4
#define HID 256
#define EMBD 512
#define NN0 49152
#define NN1 16384
#define BB 8192
#define EE0 262144
#define EE1 131072

#define TSEG (MODS * (NN1 + BB))   // 73728 total segments across 6 graphs
#define TEDG (MODS * (EE0 + EE1))  // 1179648 total edges
#define NSCANB ((TSEG + 1023) / 1024)  // 72

// ---------------- static scratch (allowed: __device__ globals) ----------------
__device__ float g_h[(size_t)NN0 * HID];      // h0 (reused as h1)
__device__ float g_s[(size_t)NN0 * HEADS];    // attention scores per source node
__device__ float g_out0[(size_t)NN1 * HID];   // block-0 GAT output
__device__ float g_gat1[(size_t)BB * HID];    // block-1 GAT output
__device__ float g_acc[(size_t)BB * HID];     // accumulated across modalities
__device__ float g_c[(size_t)EE0 * HEADS];    // per-edge coefficients alpha*val
__device__ int   g_cnt[TSEG];
__device__ int   g_indptr[TSEG + 1];
__device__ int   g_wp[TSEG];
__device__ int   g_order[TEDG];
__device__ int   g_blksum[NSCANB];
__device__ __nv_bfloat16 g_ehi[(size_t)BB * EMBD];
__device__ __nv_bfloat16 g_elo[(size_t)BB * EMBD];

// ---------------- small utility kernels ----------------
__global__ void k_zero_f(float* p, int n) {
    int i = blockIdx.x * blockDim.x + threadIdx.x;
    if (i < n) p[i] = 0.f;
}
__global__ void k_zero_i(int* p, int n) {
    int i = blockIdx.x * blockDim.x + threadIdx.x;
    if (i < n) p[i] = 0;
}

// batched histogram over all 6 graphs (3 mods x {block0, block1})
__global__ void k_hist_all(const int* __restrict__ dst0, const int* __restrict__ dst1,
                           int* cnt) {
    int i = blockIdx.x * blockDim.x + threadIdx.x;
    if (i >= TEDG) return;
    int mod = i / (EE0 + EE1);
    int rem = i - mod * (EE0 + EE1);
    int seg;
    if (rem < EE0) {
        seg = mod * (NN1 + BB) + dst0[(size_t)mod * EE0 + rem];
    } else {
        seg = mod * (NN1 + BB) + NN1 + dst1[(size_t)mod * EE1 + (rem - EE0)];
    }
    atomicAdd(&cnt[seg], 1);
}

// hierarchical scan: stage 1 — per-block exclusive scan + block sums
__global__ void k_scan1(const int* __restrict__ cnt, int n, int* indptr, int* blksum) {
    __shared__ int part[1024];
    int tid = threadIdx.x;
    int i = blockIdx.x * 1024 + tid;
    int v = (i < n) ? cnt[i] : 0;
    part[tid] = v;
    __syncthreads();
    for (int off = 1; off < 1024; off <<= 1) {
        int t = (tid >= off) ? part[tid - off] : 0;
        __syncthreads();
        part[tid] += t;
        __syncthreads();
    }
    if (i < n) indptr[i] = part[tid] - v;  // exclusive within block
    if (tid == 1023) blksum[blockIdx.x] = part[1023];
}
// stage 2 — single-block scan of block sums (nb <= 128)
__global__ void k_scan2(int* blksum, int nb, int* indptr, int n) {
    __shared__ int sh[128];
    int tid = threadIdx.x;
    int v = (tid < nb) ? blksum[tid] : 0;
    sh[tid] = v;
    __syncthreads();
    for (int off = 1; off < 128; off <<= 1) {
        int t = (tid >= off) ? sh[tid - off] : 0;
        __syncthreads();
        sh[tid] += t;
        __syncthreads();
    }
    if (tid < nb) blksum[tid] = sh[tid] - v;  // exclusive
    if (tid == 127) indptr[n] = sh[127];
}
// stage 3 — add block offsets, replicate into wp
__global__ void k_scan3(int* indptr, int* wp, const int* __restrict__ blksum, int n) {
    int i = blockIdx.x * blockDim.x + threadIdx.x;
    if (i < n) {
        int v = indptr[i] + blksum[i >> 10];
        indptr[i] = v;
        wp[i] = v;
    }
}

// batched scatter: order[] holds LOCAL edge index within its graph
__global__ void k_scatter_all(const int* __restrict__ dst0, const int* __restrict__ dst1,
                              int* wp, int* order) {
    int i = blockIdx.x * blockDim.x + threadIdx.x;
    if (i >= TEDG) return;
    int mod = i / (EE0 + EE1);
    int rem = i - mod * (EE0 + EE1);
    int seg, loc;
    if (rem < EE0) {
        loc = rem;
        seg = mod * (NN1 + BB) + dst0[(size_t)mod * EE0 + rem];
    } else {
        loc = rem - EE0;
        seg = mod * (NN1 + BB) + NN1 + dst1[(size_t)mod * EE1 + loc];
    }
    int p = atomicAdd(&wp[seg], 1);
    order[p] = loc;
}

// deterministic: restore ascending edge-id order within each segment
__global__ void k_sortseg(const int* __restrict__ indptr, int nseg, int* order) {
    int j = blockIdx.x * blockDim.x + threadIdx.x;
    if (j >= nseg) return;
    int b = indptr[j], e = indptr[j + 1];
    for (int i = b + 1; i < e; i++) {
        int v = order[i];
        int k = i - 1;
        while (k >= b && order[k] > v) { order[k + 1] = order[k]; k--; }
        order[k + 1] = v;
    }
}

// s[n,h] = sum_d h[n, h*64+d] * att[h*64+d]
__global__ void k_score(const float* __restrict__ h, const float* __restrict__ att,
                        float* __restrict__ s) {
    int r = blockIdx.x;
    int t = threadIdx.x;
    __shared__ float sh[256];
    sh[t] = h[(size_t)r * HID + t] * att[t];
    __syncthreads();
    for (int off = 32; off >= 1; off >>= 1) {
        if ((t & 63) < off) sh[t] += sh[t + off];
        __syncthreads();
    }
    if ((t & 63) == 0) s[(size_t)r * HEADS + (t >> 6)] = sh[t];
}

__device__ __forceinline__ float lrelu(float x) { return x > 0.f ? x : 0.2f * x; }

// per-segment softmax coefficients: c[e,h] = exp(lg-mx)/(den+1e-16) * vals[e]
__global__ void k_coef(const int* __restrict__ order, const int* __restrict__ indptr,
                       const int* __restrict__ src, const float* __restrict__ vals,
                       const float* __restrict__ s, float* __restrict__ c, int nseg) {
    int w = (blockIdx.x * blockDim.x + threadIdx.x) >> 5;
    int lane = threadIdx.x & 31;
    if (w >= nseg) return;
    int beg = indptr[w], end = indptr[w + 1];
    if (beg == end) return;
    float m0 = -1e30f, m1 = -1e30f, m2 = -1e30f, m3 = -1e30f;
    for (int p = beg + lane; p < end; p += 32) {
        int e = order[p];
        float4 sv = *(const float4*)(s + (size_t)src[e] * 4);
        m0 = fmaxf(m0, lrelu(sv.x)); m1 = fmaxf(m1, lrelu(sv.y));
        m2 = fmaxf(m2, lrelu(sv.z)); m3 = fmaxf(m3, lrelu(sv.w));
    }
    for (int off = 16; off; off >>= 1) {
        m0 = fmaxf(m0, __shfl_xor_sync(0xffffffffu, m0, off));
        m1 = fmaxf(m1, __shfl_xor_sync(0xffffffffu, m1, off));
        m2 = fmaxf(m2, __shfl_xor_sync(0xffffffffu, m2, off));
        m3 = fmaxf(m3, __shfl_xor_sync(0xffffffffu, m3, off));
    }
    float d0 = 0.f, d1 = 0.f, d2 = 0.f, d3 = 0.f;
    for (int p = beg + lane; p < end; p += 32) {
        int e = order[p];
        float4 sv = *(const float4*)(s + (size_t)src[e] * 4);
        d0 += expf(lrelu(sv.x) - m0); d1 += expf(lrelu(sv.y) - m1);
        d2 += expf(lrelu(sv.z) - m2); d3 += expf(lrelu(sv.w) - m3);
    }
    for (int off = 16; off; off >>= 1) {
        d0 += __shfl_xor_sync(0xffffffffu, d0, off);
        d1 += __shfl_xor_sync(0xffffffffu, d1, off);
        d2 += __shfl_xor_sync(0xffffffffu, d2, off);
        d3 += __shfl_xor_sync(0xffffffffu, d3, off);
    }
    float i0 = 1.f / (d0 + 1e-16f), i1 = 1.f / (d1 + 1e-16f);
    float i2 = 1.f / (d2 + 1e-16f), i3 = 1.f / (d3 + 1e-16f);
    for (int p = beg + lane; p < end; p += 32) {
        int e = order[p];
        float4 sv = *(const float4*)(s + (size_t)src[e] * 4);
        float v = vals[e];
        float4 cc;
        cc.x = expf(lrelu(sv.x) - m0) * i0 * v;
        cc.y = expf(lrelu(sv.y) - m1) * i1 * v;
        cc.z = expf(lrelu(sv.z) - m2) * i2 * v;
        cc.w = expf(lrelu(sv.w) - m3) * i3 * v;
        *(float4*)(c + (size_t)e * 4) = cc;
    }
}

// out[j, t] = sum_edges c[e, t/64] * h[src[e], t] + bias[t]
__global__ void k_reduce(const int* __restrict__ order, const int* __restrict__ indptr,
                         const int* __restrict__ src, const float* __restrict__ c,
                         const float* __restrict__ h, const float* __restrict__ bias,
                         float* __restrict__ out) {
    int j = blockIdx.x;
    int t = threadIdx.x;
    int head = t >> 6;
    __shared__ int ssrc[64];
    __shared__ float scoef[64 * 4];
    int beg = indptr[j], end = indptr[j + 1];
    float acc = 0.f;
    for (int ch = beg; ch < end; ch += 64) {
        int n = min(64, end - ch);
        if (t < n) {
            int e = order[ch + t];
            ssrc[t] = src[e];
            *(float4*)&scoef[t * 4] = *(const float4*)(c + (size_t)e * 4);
        }
        __syncthreads();
        for (int q = 0; q < n; q++)
            acc += scoef[q * 4 + head] * h[(size_t)ssrc[q] * HID + t];
        __syncthreads();
    }
    out[(size_t)j * HID + t] = acc + bias[t];
}

// ---------------- shared mma machinery ----------------
#define DSTRIDE 24  // smem row stride (bf16 elems): conflict-free for ldmatrix

#define LDSM4(R, ADDR)                                                        \
    asm volatile("ldmatrix.sync.aligned.m8n8.x4.shared.b16 {%0,%1,%2,%3}, [%4];" \
                 : "=r"((R)[0]), "=r"((R)[1]), "=r"((R)[2]), "=r"((R)[3])     \
                 : "r"(ADDR))

#define MMA16816(C, A, B0, B1)                                                \
    asm volatile(                                                             \
        "mma.sync.aligned.m16n8k16.row.col.f32.bf16.bf16.f32 "                \
        "{%0,%1,%2,%3},{%4,%5,%6,%7},{%8,%9},{%0,%1,%2,%3};"                  \
        : "+f"((C)[0]), "+f"((C)[1]), "+f"((C)[2]), "+f"((C)[3])              \
        : "r"((A)[0]), "r"((A)[1]), "r"((A)[2]), "r"((A)[3]), "r"(B0), "r"(B1))

// ---------------- general GEMM via bf16x3 mma ----------------
// C[M,N] = (gather(A)+abias) @ B + cbias. A:[M,K] (row-gathered), B:[K,N].
// fp32 inputs split to bf16 hi/lo in registers at smem-store time.
// Tiles: 128x128xK16, 512 threads, 4x4 warps, 32x32 warp tiles.
__global__ __launch_bounds__(512) void k_gemm_mma(
    const float* __restrict__ A, const int* __restrict__ gidx,
    const float* __restrict__ abias,
    const float* __restrict__ B, const float* __restrict__ cbias,
    float* __restrict__ C, int M, int N, int K,
    __nv_bfloat16* __restrict__ ohi, __nv_bfloat16* __restrict__ olo) {
    __shared__ __nv_bfloat16 sA[2][2][128 * DSTRIDE];  // [stage][hi/lo]
    __shared__ __nv_bfloat16 sB[2][2][128 * DSTRIDE];  // transposed: [n][k]
    int tid = threadIdx.x;
    int lane = tid & 31, wid = tid >> 5;
    int wm = wid >> 2, wn = wid & 3;
    int bm = blockIdx.y * 128, bn = blockIdx.x * 128;

    // A: row = tid>>2 (0..127), col = (tid&3)*4
    int arow = tid >> 2;
    int acol = (tid & 3) * 4;
    size_t abase = (size_t)(gidx ? gidx[bm + arow] : (bm + arow)) * K + acol;
    int asoff = arow * DSTRIDE + acol;
    // B: krow = tid>>5 (0..15), ncol = (tid&31)*4
    int bkrow = tid >> 5;
    int bncol = (tid & 31) * 4;

    int lrow = (lane & 7) + ((lane >> 3) & 1) * 8;
    int lcol = (lane >> 4) * 8;

    float acc[2][4][4];
#pragma unroll
    for (int m = 0; m < 2; m++)
#pragma unroll
        for (int n = 0; n < 4; n++)
#pragma unroll
            for (int q = 0; q < 4; q++) acc[m][n][q] = 0.f;

    int niter = K / 16;
    float4 av, bv;

    // load tile 0
    av = *(const float4*)(A + abase);
    if (abias) {
        float4 t = *(const float4*)(abias + acol);
        av.x += t.x; av.y += t.y; av.z += t.z; av.w += t.w;
    }
    bv = *(const float4*)(B + (size_t)bkrow * N + bn + bncol);
    // store tile 0 -> stage 0
    {
        __nv_bfloat16 h0 = __float2bfloat16(av.x), h1 = __float2bfloat16(av.y);
        __nv_bfloat16 h2 = __float2bfloat16(av.z), h3 = __float2bfloat16(av.w);
        *(__nv_bfloat162*)&sA[0][0][asoff] = __nv_bfloat162(h0, h1);
        *(__nv_bfloat162*)&sA[0][0][asoff + 2] = __nv_bfloat162(h2, h3);
        *(__nv_bfloat162*)&sA[0][1][asoff] = __nv_bfloat162(
            __float2bfloat16(av.x - __bfloat162float(h0)),
            __float2bfloat16(av.y - __bfloat162float(h1)));
        *(__nv_bfloat162*)&sA[0][1][asoff + 2] = __nv_bfloat162(
            __float2bfloat16(av.z - __bfloat162float(h2)),
            __float2bfloat16(av.w - __bfloat162float(h3)));
        const float* bp = &bv.x;
#pragma unroll
        for (int i = 0; i < 4; i++) {
            float f = bp[i];
            __nv_bfloat16 hb = __float2bfloat16(f);
            sB[0][0][(bncol + i) * DSTRIDE + bkrow] = hb;
            sB[0][1][(bncol + i) * DSTRIDE + bkrow] =
                __float2bfloat16(f - __bfloat162float(hb));
        }
    }
    __syncthreads();

    for (int it = 0; it < niter; it++) {
        int st = it & 1;
        // prefetch next tile into regs (overlap with mma)
        if (it + 1 < niter) {
            av = *(const float4*)(A + abase + (size_t)(it + 1) * 16);
            if (abias) {
                float4 t = *(const float4*)(abias + (it + 1) * 16 + acol);
                av.x += t.x; av.y += t.y; av.z += t.z; av.w += t.w;
            }
            bv = *(const float4*)(B + (size_t)((it + 1) * 16 + bkrow) * N + bn + bncol);
        }
        uint32_t fa[2][2][4], fb[2][2][4];
#pragma unroll
        for (int mt = 0; mt < 2; mt++)
#pragma unroll
            for (int op = 0; op < 2; op++) {
                uint32_t ad = (uint32_t)__cvta_generic_to_shared(
                    &sA[st][op][(wm * 32 + mt * 16 + lrow) * DSTRIDE + lcol]);
                LDSM4(fa[mt][op], ad);
            }
#pragma unroll
        for (int np = 0; np < 2; np++)
#pragma unroll
            for (int op = 0; op < 2; op++) {
                uint32_t ad = (uint32_t)__cvta_generic_to_shared(
                    &sB[st][op][(wn * 32 + np * 16 + lrow) * DSTRIDE + lcol]);
                LDSM4(fb[np][op], ad);
            }
#pragma unroll
        for (int mt = 0; mt < 2; mt++)
#pragma unroll
            for (int np = 0; np < 2; np++)
#pragma unroll
                for (int s = 0; s < 2; s++) {
                    int nt = np * 2 + s;
                    MMA16816(acc[mt][nt], fa[mt][0], fb[np][0][s], fb[np][0][2 + s]);
                    MMA16816(acc[mt][nt], fa[mt][0], fb[np][1][s], fb[np][1][2 + s]);
                    MMA16816(acc[mt][nt], fa[mt][1], fb[np][0][s], fb[np][0][2 + s]);
                }
        if (it + 1 < niter) {
            int ns = st ^ 1;
            __nv_bfloat16 h0 = __float2bfloat16(av.x), h1 = __float2bfloat16(av.y);
            __nv_bfloat16 h2 = __float2bfloat16(av.z), h3 = __float2bfloat16(av.w);
            *(__nv_bfloat162*)&sA[ns][0][asoff] = __nv_bfloat162(h0, h1);
            *(__nv_bfloat162*)&sA[ns][0][asoff + 2] = __nv_bfloat162(h2, h3);
            *(__nv_bfloat162*)&sA[ns][1][asoff] = __nv_bfloat162(
                __float2bfloat16(av.x - __bfloat162float(h0)),
                __float2bfloat16(av.y - __bfloat162float(h1)));
            *(__nv_bfloat162*)&sA[ns][1][asoff + 2] = __nv_bfloat162(
                __float2bfloat16(av.z - __bfloat162float(h2)),
                __float2bfloat16(av.w - __bfloat162float(h3)));
            const float* bp = &bv.x;
#pragma unroll
            for (int i = 0; i < 4; i++) {
                float f = bp[i];
                __nv_bfloat16 hb = __float2bfloat16(f);
                sB[ns][0][(bncol + i) * DSTRIDE + bkrow] = hb;
                sB[ns][1][(bncol + i) * DSTRIDE + bkrow] =
                    __float2bfloat16(f - __bfloat162float(hb));
            }
        }
        __syncthreads();
    }

    // epilogue
#pragma unroll
    for (int mt = 0; mt < 2; mt++) {
        int r0 = bm + wm * 32 + mt * 16 + (lane >> 2);
#pragma unroll
        for (int nt = 0; nt < 4; nt++) {
            int cc = bn + wn * 32 + nt * 8 + (lane & 3) * 2;
            float2 v0 = {acc[mt][nt][0], acc[mt][nt][1]};
            float2 v1 = {acc[mt][nt][2], acc[mt][nt][3]};
            if (cbias) {
                float cb0 = cbias[cc], cb1 = cbias[cc + 1];
                v0.x += cb0; v0.y += cb1;
                v1.x += cb0; v1.y += cb1;
            }
            size_t p0 = (size_t)r0 * N + cc;
            size_t p1 = (size_t)(r0 + 8) * N + cc;
            *(float2*)(C + p0) = v0;
            *(float2*)(C + p1) = v1;
            if (ohi) {
                __nv_bfloat16 a0 = __float2bfloat16(v0.x), a1 = __float2bfloat16(v0.y);
                __nv_bfloat16 b0 = __float2bfloat16(v1.x), b1 = __float2bfloat16(v1.y);
                *(__nv_bfloat162*)(ohi + p0) = __nv_bfloat162(a0, a1);
                *(__nv_bfloat162*)(ohi + p1) = __nv_bfloat162(b0, b1);
                *(__nv_bfloat162*)(olo + p0) = __nv_bfloat162(
                    __float2bfloat16(v0.x - __bfloat162float(a0)),
                    __float2bfloat16(v0.y - __bfloat162float(a1)));
                *(__nv_bfloat162*)(olo + p1) = __nv_bfloat162(
                    __float2bfloat16(v1.x - __bfloat162float(b0)),
                    __float2bfloat16(v1.y - __bfloat162float(b1)));
            }
        }
    }
}

// ---------------- NT GEMM via bf16x3 mma, symmetric: C = E @ E^T, K=512 --------
__global__ __launch_bounds__(512) void k_dot_mma(
    const __nv_bfloat16* __restrict__ Ehi, const __nv_bfloat16* __restrict__ Elo,
    float* __restrict__ C) {
    __shared__ __nv_bfloat16 sA[2][2][128 * DSTRIDE];  // [stage][hi/lo]
    __shared__ __nv_bfloat16 sB[2][2][128 * DSTRIDE];
    int tid = threadIdx.x;
    int lane = tid & 31, wid = tid >> 5;
    int wm = wid >> 2, wn = wid & 3;  // 4x4 warps, 32x32 tile each

    // triangular block decode: blockIdx.x in [0, 64*65/2)
    int bid = blockIdx.x;
    int brow = (int)((sqrtf(8.0f * (float)bid + 1.0f) - 1.0f) * 0.5f);
    while ((brow + 1) * (brow + 2) / 2 <= bid) brow++;
    while (brow * (brow + 1) / 2 > bid) brow--;
    int bcol = bid - brow * (brow + 1) / 2;
    int bi = brow * 128, bj = bcol * 128;  // bi >= bj

    int grow = tid >> 2;
    int gcol = (tid & 3) * 4;
    const __nv_bfloat16* pAhi = Ehi + (size_t)(bi + grow) * EMBD + gcol;
    const __nv_bfloat16* pAlo = Elo + (size_t)(bi + grow) * EMBD + gcol;
    const __nv_bfloat16* pBhi = Ehi + (size_t)(bj + grow) * EMBD + gcol;
    const __nv_bfloat16* pBlo = Elo + (size_t)(bj + grow) * EMBD + gcol;
    int soff = grow * DSTRIDE + gcol;

    int lrow = (lane & 7) + ((lane >> 3) & 1) * 8;
    int lcol = (lane >> 4) * 8;

    float acc[2][4][4];
#pragma unroll
    for (int m = 0; m < 2; m++)
#pragma unroll
        for (int n = 0; n < 4; n++)
#pragma unroll
            for (int q = 0; q < 4; q++) acc[m][n][q] = 0.f;

    uint2 vah = *(const uint2*)pAhi;
    uint2 val = *(const uint2*)pAlo;
    uint2 vbh = *(const uint2*)pBhi;
    uint2 vbl = *(const uint2*)pBlo;
    *(uint2*)&sA[0][0][soff] = vah;
    *(uint2*)&sA[0][1][soff] = val;
    *(uint2*)&sB[0][0][soff] = vbh;
    *(uint2*)&sB[0][1][soff] = vbl;
    vah = *(const uint2*)(pAhi + 16);
    val = *(const uint2*)(pAlo + 16);
    vbh = *(const uint2*)(pBhi + 16);
    vbl = *(const uint2*)(pBlo + 16);
    __syncthreads();

    for (int it = 0; it < EMBD / 16; it++) {
        int st = it & 1;
        uint32_t fa[2][2][4], fb[2][2][4];
#pragma unroll
        for (int mt = 0; mt < 2; mt++)
#pragma unroll
            for (int op = 0; op < 2; op++) {
                uint32_t ad = (uint32_t)__cvta_generic_to_shared(
                    &sA[st][op][(wm * 32 + mt * 16 + lrow) * DSTRIDE + lcol]);
                LDSM4(fa[mt][op], ad);
            }
#pragma unroll
        for (int np = 0; np < 2; np++)
#pragma unroll
            for (int op = 0; op < 2; op++) {
                uint32_t ad = (uint32_t)__cvta_generic_to_shared(
                    &sB[st][op][(wn * 32 + np * 16 + lrow) * DSTRIDE + lcol]);
                LDSM4(fb[np][op], ad);
            }
        if (it < EMBD / 16 - 1) {
            int ns = st ^ 1;
            *(uint2*)&sA[ns][0][soff] = vah;
            *(uint2*)&sA[ns][1][soff] = val;
            *(uint2*)&sB[ns][0][soff] = vbh;
            *(uint2*)&sB[ns][1][soff] = vbl;
        }
        __syncthreads();
        if (it < EMBD / 16 - 2) {
            vah = *(const uint2*)(pAhi + (it + 2) * 16);
            val = *(const uint2*)(pAlo + (it + 2) * 16);
            vbh = *(const uint2*)(pBhi + (it + 2) * 16);
            vbl = *(const uint2*)(pBlo + (it + 2) * 16);
        }
#pragma unroll
        for (int mt = 0; mt < 2; mt++)
#pragma unroll
            for (int np = 0; np < 2; np++)
#pragma unroll
                for (int s = 0; s < 2; s++) {
                    int nt = np * 2 + s;
                    MMA16816(acc[mt][nt], fa[mt][0], fb[np][0][s], fb[np][0][2 + s]);
                    MMA16816(acc[mt][nt], fa[mt][0], fb[np][1][s], fb[np][1][2 + s]);
                    MMA16816(acc[mt][nt], fa[mt][1], fb[np][0][s], fb[np][0][2 + s]);
                }
    }

    // epilogue: direct tile + mirrored (transposed) tile for off-diagonal blocks
#pragma unroll
    for (int mt = 0; mt < 2; mt++) {
        int r0 = bi + wm * 32 + mt * 16 + (lane >> 2);
#pragma unroll
        for (int nt = 0; nt < 4; nt++) {
            int cc = bj + wn * 32 + nt * 8 + (lane & 3) * 2;
            float2 v0 = {acc[mt][nt][0], acc[mt][nt][1]};
            float2 v1 = {acc[mt][nt][2], acc[mt][nt][3]};
            *(float2*)(C + (size_t)r0 * BB + cc) = v0;
            *(float2*)(C + (size_t)(r0 + 8) * BB + cc) = v1;
            if (bi != bj) {
                C[(size_t)cc * BB + r0] = acc[mt][nt][0];
                C[(size_t)(cc + 1) * BB + r0] = acc[mt][nt][1];
                C[(size_t)cc * BB + r0 + 8] = acc[mt][nt][2];
                C[(size_t)(cc + 1) * BB + r0 + 8] = acc[mt][nt][3];
            }
        }
    }
}

// skip connection + interpolation accumulate
__global__ void k_accum(const float* __restrict__ out0, const int* __restrict__ res,
                        const float* __restrict__ gat1, const float* __restrict__ masks,
                        const float* __restrict__ iw, int mod, float* __restrict__ acc) {
    int b = blockIdx.x;
    int t = threadIdx.x;
    __shared__ float coef;
    __shared__ int rid;
    if (t == 0) {
        float w0 = iw[0], w1 = iw[1], w2 = iw[2];
        float mw = fmaxf(w0, fmaxf(w1, w2));
        float e0 = expf(w0 - mw), e1 = expf(w1 - mw), e2 = expf(w2 - mw);
        float ws = e0 + e1 + e2;
        float wi = (mod == 0 ? e0 : (mod == 1 ? e1 : e2)) / ws;
        float m0 = masks[b * 3 + 0], m1 = masks[b * 3 + 1], m2 = masks[b * 3 + 2];
        float msum = m0 + m1 + m2;
        float r = 1.0f + 1.0f / powf(1.0f + 3.0f, 20.0f) + 1.0f / powf(msum, 20.0f);
        r = floorf(r);
        r = r / (r + 1e-10f);
        float z0 = m0 * r, z1 = m1 * r, z2 = m2 * r;
        z0 = z0 + (1.0f - z0) * (-1e10f);
        z1 = z1 + (1.0f - z1) * (-1e10f);
        z2 = z2 + (1.0f - z2) * (-1e10f);
        float zm = fmaxf(z0, fmaxf(z1, z2));
        float x0 = expf(z0 - zm), x1 = expf(z1 - zm), x2 = expf(z2 - zm);
        float xs = x0 + x1 + x2;
        float im = (mod == 0 ? x0 : (mod == 1 ? x1 : x2)) / xs;
        coef = wi * im;
        rid = res[b];
    }
    __syncthreads();
    acc[(size_t)b * HID + t] += coef * (out0[(size_t)rid * HID + t] + gat1[(size_t)b * HID + t]);
}

__global__ void k_weights(const float* __restrict__ iw, float* __restrict__ o) {
    float w0 = iw[0], w1 = iw[1], w2 = iw[2];
    float m = fmaxf(w0, fmaxf(w1, w2));
    float e0 = expf(w0 - m), e1 = expf(w1 - m), e2 = expf(w2 - m);
    float s = e0 + e1 + e2;
    o[0] = e0 / s; o[1] = e1 / s; o[2] = e2 / s;
}

extern "C" void kernel_launch(void* const* d_in, const int* in_sizes, int n_in,
                              void* d_out, int out_size) {
    const int*   n_id     = (const int*)d_in[0];
    const int*   src0     = (const int*)d_in[1];
    const int*   dst0     = (const int*)d_in[2];
    const int*   src1     = (const int*)d_in[3];
    const int*   dst1     = (const int*)d_in[4];
    const int*   res_n_id = (const int*)d_in[5];
    const float* vals0    = (const float*)d_in[6];
    const float* vals1    = (const float*)d_in[7];
    const float* masks    = (const float*)d_in[8];
    const float* pre_W    = (const float*)d_in[9];
    const float* pre_b    = (const float*)d_in[10];
    const float* W_gat    = (const float*)d_in[11];
    const float* att      = (const float*)d_in[12];
    const float* gat_b    = (const float*)d_in[13];
    const float* interp_w = (const float*)d_in[14];
    const float* emb_W    = (const float*)d_in[15];
    const float* emb_b    = (const float*)d_in[16];

    float* dot = (float*)d_out;
    float* emb = dot + (size_t)BB * BB;
    float* wout = emb + (size_t)BB * EMBD;

    float *h, *s, *out0, *gat1, *acc, *c;
    int *cnt, *indptr, *wp, *order, *blksum;
    __nv_bfloat16 *ehi, *elo;
    cudaGetSymbolAddress((void**)&h, g_h);
    cudaGetSymbolAddress((void**)&s, g_s);
    cudaGetSymbolAddress((void**)&out0, g_out0);
    cudaGetSymbolAddress((void**)&gat1, g_gat1);
    cudaGetSymbolAddress((void**)&acc, g_acc);
    cudaGetSymbolAddress((void**)&c, g_c);
    cudaGetSymbolAddress((void**)&cnt, g_cnt);
    cudaGetSymbolAddress((void**)&indptr, g_indptr);
    cudaGetSymbolAddress((void**)&wp, g_wp);
    cudaGetSymbolAddress((void**)&order, g_order);
    cudaGetSymbolAddress((void**)&blksum, g_blksum);
    cudaGetSymbolAddress((void**)&ehi, g_ehi);
    cudaGetSymbolAddress((void**)&elo, g_elo);

    k_zero_f<<<(BB * HID + 255) / 256, 256>>>(acc, BB * HID);

    // ---- batched CSR build for all 6 graphs ----
    k_zero_i<<<(TSEG + 255) / 256, 256>>>(cnt, TSEG);
    k_hist_all<<<(TEDG + 255) / 256, 256>>>(dst0, dst1, cnt);
    k_scan1<<<NSCANB, 1024>>>(cnt, TSEG, indptr, blksum);
    k_scan2<<<1, 128>>>(blksum, NSCANB, indptr, TSEG);
    k_scan3<<<(TSEG + 255) / 256, 256>>>(indptr, wp, blksum, TSEG);
    k_scatter_all<<<(TEDG + 255) / 256, 256>>>(dst0, dst1, wp, order);
    k_sortseg<<<(TSEG + 255) / 256, 256>>>(indptr, TSEG, order);

    const int IN_SZ = 50000;
    for (int i = 0; i < MODS; i++) {
        const float* Wg  = W_gat + (size_t)i * HID * HID;
        const float* ai  = att + (size_t)i * HID;
        const float* gbi = gat_b + (size_t)i * HID;
        const int* ip0 = indptr + i * (NN1 + BB);
        const int* ip1 = indptr + i * (NN1 + BB) + NN1;

        // ---- block 0: N0 sources -> N1 targets ----
        const int* s0 = src0 + (size_t)i * EE0;
        {   // h0 = (pre_W[i][n_id] + pre_b[i]) @ Wg
            dim3 grid(HID / 128, NN0 / 128);
            k_gemm_mma<<<grid, 512>>>(pre_W + (size_t)i * IN_SZ * HID,
                                      n_id + (size_t)i * NN0,
                                      pre_b + (size_t)i * HID,
                                      Wg, nullptr, h, NN0, HID, HID,
                                      nullptr, nullptr);
        }
        k_score<<<NN0, 256>>>(h, ai, s);
        k_coef<<<(NN1 * 32 + 255) / 256, 256>>>(order, ip0, s0,
                                                vals0 + (size_t)i * EE0, s, c, NN1);
        k_reduce<<<NN1, 256>>>(order, ip0, s0, c, h, gbi, out0);

        // ---- block 1: N1 sources -> B targets ----
        const int* s1 = src1 + (size_t)i * EE1;
        {   // h1 = out0 @ Wg
            dim3 grid(HID / 128, NN1 / 128);
            k_gemm_mma<<<grid, 512>>>(out0, nullptr, nullptr, Wg, nullptr, h,
                                      NN1, HID, HID, nullptr, nullptr);
        }
        k_score<<<NN1, 256>>>(h, ai, s);
        k_coef<<<(BB * 32 + 255) / 256, 256>>>(order, ip1, s1,
                                               vals1 + (size_t)i * EE1, s, c, BB);
        k_reduce<<<BB, 256>>>(order, ip1, s1, c, h, gbi, gat1);

        // ---- skip + interpolation accumulate ----
        k_accum<<<BB, 256>>>(out0, res_n_id + (size_t)i * BB, gat1, masks,
                             interp_w, i, acc);
    }

    // emb = acc @ emb_W + emb_b  (+ fused bf16 hi/lo split)
    {
        dim3 grid(EMBD / 128, BB / 128);
        k_gemm_mma<<<grid, 512>>>(acc, nullptr, nullptr, emb_W, emb_b, emb,
                                  BB, EMBD, HID, ehi, elo);
    }
    // dot = emb @ emb^T via bf16x3 tensor-core emulation, symmetric half-grid
    {
        int npairs = (BB / 128) * (BB / 128 + 1) / 2;  // 2080
        k_dot_mma<<<npairs, 512>>>(ehi, elo, dot);
    }
    k_weights<<<1, 1>>>(interp_w, wout);
}

// round 6
// speedup vs baseline: 2.2426x; 1.2727x over previous
#include <cuda_runtime.h>
#include <cuda_bf16.h>
#include <cstdint>
#include <math.h>

#define MODS 3
#define HEADS 4
#define HID 256
#define EMBD 512
#define NN0 49152
#define NN1 16384
#define BB 8192
#define EE0 262144
#define EE1 131072

#define TSEG (MODS * (NN1 + BB))   // 73728 total segments across 6 graphs
#define TEDG (MODS * (EE0 + EE1))  // 1179648 total edges
#define NSCANB ((TSEG + 1023) / 1024)  // 72

// ---------------- static scratch (allowed: __device__ globals) ----------------
__device__ float g_h[(size_t)NN0 * HID];      // h0 (reused as h1)
__device__ float g_s[(size_t)NN0 * HEADS];    // attention scores per source node
__device__ float g_out0[(size_t)NN1 * HID];   // block-0 GAT output
__device__ float g_gat1[(size_t)BB * HID];    // block-1 GAT output
__device__ float g_acc[(size_t)BB * HID];     // accumulated across modalities
__device__ float g_c[(size_t)EE0 * HEADS];    // per-edge coefficients alpha*val
__device__ int   g_cnt[TSEG];
__device__ int   g_indptr[TSEG + 1];
__device__ int   g_wp[TSEG];
__device__ int   g_order[TEDG];
__device__ int   g_blksum[NSCANB];
__device__ __nv_bfloat16 g_ehi[(size_t)BB * EMBD];
__device__ __nv_bfloat16 g_elo[(size_t)BB * EMBD];

// ---------------- small utility kernels ----------------
__global__ void k_zero_f(float* p, int n) {
    int i = blockIdx.x * blockDim.x + threadIdx.x;
    if (i < n) p[i] = 0.f;
}
__global__ void k_zero_i(int* p, int n) {
    int i = blockIdx.x * blockDim.x + threadIdx.x;
    if (i < n) p[i] = 0;
}

// batched histogram over all 6 graphs (3 mods x {block0, block1})
__global__ void k_hist_all(const int* __restrict__ dst0, const int* __restrict__ dst1,
                           int* cnt) {
    int i = blockIdx.x * blockDim.x + threadIdx.x;
    if (i >= TEDG) return;
    int mod = i / (EE0 + EE1);
    int rem = i - mod * (EE0 + EE1);
    int seg;
    if (rem < EE0) {
        seg = mod * (NN1 + BB) + dst0[(size_t)mod * EE0 + rem];
    } else {
        seg = mod * (NN1 + BB) + NN1 + dst1[(size_t)mod * EE1 + (rem - EE0)];
    }
    atomicAdd(&cnt[seg], 1);
}

// hierarchical scan: stage 1 — per-block exclusive scan + block sums
__global__ void k_scan1(const int* __restrict__ cnt, int n, int* indptr, int* blksum) {
    __shared__ int part[1024];
    int tid = threadIdx.x;
    int i = blockIdx.x * 1024 + tid;
    int v = (i < n) ? cnt[i] : 0;
    part[tid] = v;
    __syncthreads();
    for (int off = 1; off < 1024; off <<= 1) {
        int t = (tid >= off) ? part[tid - off] : 0;
        __syncthreads();
        part[tid] += t;
        __syncthreads();
    }
    if (i < n) indptr[i] = part[tid] - v;  // exclusive within block
    if (tid == 1023) blksum[blockIdx.x] = part[1023];
}
// stage 2 — single-block scan of block sums (nb <= 128)
__global__ void k_scan2(int* blksum, int nb, int* indptr, int n) {
    __shared__ int sh[128];
    int tid = threadIdx.x;
    int v = (tid < nb) ? blksum[tid] : 0;
    sh[tid] = v;
    __syncthreads();
    for (int off = 1; off < 128; off <<= 1) {
        int t = (tid >= off) ? sh[tid - off] : 0;
        __syncthreads();
        sh[tid] += t;
        __syncthreads();
    }
    if (tid < nb) blksum[tid] = sh[tid] - v;  // exclusive
    if (tid == 127) indptr[n] = sh[127];
}
// stage 3 — add block offsets, replicate into wp
__global__ void k_scan3(int* indptr, int* wp, const int* __restrict__ blksum, int n) {
    int i = blockIdx.x * blockDim.x + threadIdx.x;
    if (i < n) {
        int v = indptr[i] + blksum[i >> 10];
        indptr[i] = v;
        wp[i] = v;
    }
}

// batched scatter: order[] holds LOCAL edge index within its graph
__global__ void k_scatter_all(const int* __restrict__ dst0, const int* __restrict__ dst1,
                              int* wp, int* order) {
    int i = blockIdx.x * blockDim.x + threadIdx.x;
    if (i >= TEDG) return;
    int mod = i / (EE0 + EE1);
    int rem = i - mod * (EE0 + EE1);
    int seg, loc;
    if (rem < EE0) {
        loc = rem;
        seg = mod * (NN1 + BB) + dst0[(size_t)mod * EE0 + rem];
    } else {
        loc = rem - EE0;
        seg = mod * (NN1 + BB) + NN1 + dst1[(size_t)mod * EE1 + loc];
    }
    int p = atomicAdd(&wp[seg], 1);
    order[p] = loc;
}

// deterministic: restore ascending edge-id order within each segment
__global__ void k_sortseg(const int* __restrict__ indptr, int nseg, int* order) {
    int j = blockIdx.x * blockDim.x + threadIdx.x;
    if (j >= nseg) return;
    int b = indptr[j], e = indptr[j + 1];
    for (int i = b + 1; i < e; i++) {
        int v = order[i];
        int k = i - 1;
        while (k >= b && order[k] > v) { order[k + 1] = order[k]; k--; }
        order[k + 1] = v;
    }
}

// s[n,h] = sum_d h[n, h*64+d] * att[h*64+d]
__global__ void k_score(const float* __restrict__ h, const float* __restrict__ att,
                        float* __restrict__ s) {
    int r = blockIdx.x;
    int t = threadIdx.x;
    __shared__ float sh[256];
    sh[t] = h[(size_t)r * HID + t] * att[t];
    __syncthreads();
    for (int off = 32; off >= 1; off >>= 1) {
        if ((t & 63) < off) sh[t] += sh[t + off];
        __syncthreads();
    }
    if ((t & 63) == 0) s[(size_t)r * HEADS + (t >> 6)] = sh[t];
}

__device__ __forceinline__ float lrelu(float x) { return x > 0.f ? x : 0.2f * x; }

// per-segment softmax coefficients: c[e,h] = exp(lg-mx)/(den+1e-16) * vals[e]
__global__ void k_coef(const int* __restrict__ order, const int* __restrict__ indptr,
                       const int* __restrict__ src, const float* __restrict__ vals,
                       const float* __restrict__ s, float* __restrict__ c, int nseg) {
    int w = (blockIdx.x * blockDim.x + threadIdx.x) >> 5;
    int lane = threadIdx.x & 31;
    if (w >= nseg) return;
    int beg = indptr[w], end = indptr[w + 1];
    if (beg == end) return;
    float m0 = -1e30f, m1 = -1e30f, m2 = -1e30f, m3 = -1e30f;
    for (int p = beg + lane; p < end; p += 32) {
        int e = order[p];
        float4 sv = *(const float4*)(s + (size_t)src[e] * 4);
        m0 = fmaxf(m0, lrelu(sv.x)); m1 = fmaxf(m1, lrelu(sv.y));
        m2 = fmaxf(m2, lrelu(sv.z)); m3 = fmaxf(m3, lrelu(sv.w));
    }
    for (int off = 16; off; off >>= 1) {
        m0 = fmaxf(m0, __shfl_xor_sync(0xffffffffu, m0, off));
        m1 = fmaxf(m1, __shfl_xor_sync(0xffffffffu, m1, off));
        m2 = fmaxf(m2, __shfl_xor_sync(0xffffffffu, m2, off));
        m3 = fmaxf(m3, __shfl_xor_sync(0xffffffffu, m3, off));
    }
    float d0 = 0.f, d1 = 0.f, d2 = 0.f, d3 = 0.f;
    for (int p = beg + lane; p < end; p += 32) {
        int e = order[p];
        float4 sv = *(const float4*)(s + (size_t)src[e] * 4);
        d0 += expf(lrelu(sv.x) - m0); d1 += expf(lrelu(sv.y) - m1);
        d2 += expf(lrelu(sv.z) - m2); d3 += expf(lrelu(sv.w) - m3);
    }
    for (int off = 16; off; off >>= 1) {
        d0 += __shfl_xor_sync(0xffffffffu, d0, off);
        d1 += __shfl_xor_sync(0xffffffffu, d1, off);
        d2 += __shfl_xor_sync(0xffffffffu, d2, off);
        d3 += __shfl_xor_sync(0xffffffffu, d3, off);
    }
    float i0 = 1.f / (d0 + 1e-16f), i1 = 1.f / (d1 + 1e-16f);
    float i2 = 1.f / (d2 + 1e-16f), i3 = 1.f / (d3 + 1e-16f);
    for (int p = beg + lane; p < end; p += 32) {
        int e = order[p];
        float4 sv = *(const float4*)(s + (size_t)src[e] * 4);
        float v = vals[e];
        float4 cc;
        cc.x = expf(lrelu(sv.x) - m0) * i0 * v;
        cc.y = expf(lrelu(sv.y) - m1) * i1 * v;
        cc.z = expf(lrelu(sv.z) - m2) * i2 * v;
        cc.w = expf(lrelu(sv.w) - m3) * i3 * v;
        *(float4*)(c + (size_t)e * 4) = cc;
    }
}

// out[j, t] = sum_edges c[e, t/64] * h[src[e], t] + bias[t]
__global__ void k_reduce(const int* __restrict__ order, const int* __restrict__ indptr,
                         const int* __restrict__ src, const float* __restrict__ c,
                         const float* __restrict__ h, const float* __restrict__ bias,
                         float* __restrict__ out) {
    int j = blockIdx.x;
    int t = threadIdx.x;
    int head = t >> 6;
    __shared__ int ssrc[64];
    __shared__ float scoef[64 * 4];
    int beg = indptr[j], end = indptr[j + 1];
    float acc = 0.f;
    for (int ch = beg; ch < end; ch += 64) {
        int n = min(64, end - ch);
        if (t < n) {
            int e = order[ch + t];
            ssrc[t] = src[e];
            *(float4*)&scoef[t * 4] = *(const float4*)(c + (size_t)e * 4);
        }
        __syncthreads();
        for (int q = 0; q < n; q++)
            acc += scoef[q * 4 + head] * h[(size_t)ssrc[q] * HID + t];
        __syncthreads();
    }
    out[(size_t)j * HID + t] = acc + bias[t];
}

// ---------------- shared mma machinery ----------------
#define DSTRIDE 24   // A-tile smem row stride (bf16): conflict-free for ldmatrix
#define BPAD 136     // B-tile [k][n] row stride (bf16): conflict-free for trans ldmatrix

#define LDSM4(R, ADDR)                                                        \
    asm volatile("ldmatrix.sync.aligned.m8n8.x4.shared.b16 {%0,%1,%2,%3}, [%4];" \
                 : "=r"((R)[0]), "=r"((R)[1]), "=r"((R)[2]), "=r"((R)[3])     \
                 : "r"(ADDR))

#define LDSM4T(R, ADDR)                                                       \
    asm volatile("ldmatrix.sync.aligned.m8n8.x4.trans.shared.b16 {%0,%1,%2,%3}, [%4];" \
                 : "=r"((R)[0]), "=r"((R)[1]), "=r"((R)[2]), "=r"((R)[3])     \
                 : "r"(ADDR))

#define MMA16816(C, A, B0, B1)                                                \
    asm volatile(                                                             \
        "mma.sync.aligned.m16n8k16.row.col.f32.bf16.bf16.f32 "                \
        "{%0,%1,%2,%3},{%4,%5,%6,%7},{%8,%9},{%0,%1,%2,%3};"                  \
        : "+f"((C)[0]), "+f"((C)[1]), "+f"((C)[2]), "+f"((C)[3])              \
        : "r"((A)[0]), "r"((A)[1]), "r"((A)[2]), "r"((A)[3]), "r"(B0), "r"(B1))

__device__ __forceinline__ __nv_bfloat162 bfhi2(float a, float b,
                                                __nv_bfloat16& ha, __nv_bfloat16& hb) {
    ha = __float2bfloat16(a);
    hb = __float2bfloat16(b);
    return __nv_bfloat162(ha, hb);
}

// ---------------- general GEMM via bf16x3 mma ----------------
// C[M,N] = (gather(A)+abias) @ B + cbias. A:[M,K] row-gathered, B:[K,N].
// B stored in smem as [k][n] rows (vectorized, conflict-free) and consumed
// via ldmatrix.trans. Tiles: 128x128xK16, 512 threads, 4x4 warps.
__global__ __launch_bounds__(512) void k_gemm_mma(
    const float* __restrict__ A, const int* __restrict__ gidx,
    const float* __restrict__ abias,
    const float* __restrict__ B, const float* __restrict__ cbias,
    float* __restrict__ C, int M, int N, int K,
    __nv_bfloat16* __restrict__ ohi, __nv_bfloat16* __restrict__ olo) {
    __shared__ __nv_bfloat16 sA[2][2][128 * DSTRIDE];  // [stage][hi/lo]
    __shared__ __nv_bfloat16 sB[2][2][16 * BPAD];      // [stage][hi/lo], [k][n]
    int tid = threadIdx.x;
    int lane = tid & 31, wid = tid >> 5;
    int wm = wid >> 2, wn = wid & 3;
    int bm = blockIdx.y * 128, bn = blockIdx.x * 128;

    // A: row = tid>>2 (0..127), col = (tid&3)*4
    int arow = tid >> 2;
    int acol = (tid & 3) * 4;
    size_t abase = (size_t)(gidx ? gidx[bm + arow] : (bm + arow)) * K + acol;
    int asoff = arow * DSTRIDE + acol;
    // B: krow = tid>>5 (0..15), ncol = (tid&31)*4
    int bkrow = tid >> 5;
    int bncol = (tid & 31) * 4;
    int bsoff = bkrow * BPAD + bncol;

    // A ldmatrix addressing (non-trans): lanes 0-7 rows 0-7 col0, 8-15 rows 8-15,
    // 16-23 rows 0-7 col8, 24-31 rows 8-15 col8 -> frags (m0k0,m8k0,m0k8,m8k8)
    int alrow = (lane & 7) + ((lane >> 3) & 1) * 8;
    int alcol = (lane >> 4) * 8;
    // B trans-ldmatrix addressing: lanes 0-15 k-rows 0-15 at ncol0, 16-31 at ncol8
    // -> post-trans frags (n0k0, n0k8, n8k0, n8k8): slice s uses (r[2s], r[2s+1])
    int blrow = lane & 15;
    int blcol = (lane >> 4) * 8;

    float acc[2][4][4];
#pragma unroll
    for (int m = 0; m < 2; m++)
#pragma unroll
        for (int n = 0; n < 4; n++)
#pragma unroll
            for (int q = 0; q < 4; q++) acc[m][n][q] = 0.f;

    int niter = K / 16;
    float4 av, bv;

    // load + store tile 0 -> stage 0
    av = *(const float4*)(A + abase);
    if (abias) {
        float4 t = *(const float4*)(abias + acol);
        av.x += t.x; av.y += t.y; av.z += t.z; av.w += t.w;
    }
    bv = *(const float4*)(B + (size_t)bkrow * N + bn + bncol);
    {
        __nv_bfloat16 h0, h1, h2, h3;
        *(__nv_bfloat162*)&sA[0][0][asoff] = bfhi2(av.x, av.y, h0, h1);
        *(__nv_bfloat162*)&sA[0][0][asoff + 2] = bfhi2(av.z, av.w, h2, h3);
        *(__nv_bfloat162*)&sA[0][1][asoff] = __nv_bfloat162(
            __float2bfloat16(av.x - __bfloat162float(h0)),
            __float2bfloat16(av.y - __bfloat162float(h1)));
        *(__nv_bfloat162*)&sA[0][1][asoff + 2] = __nv_bfloat162(
            __float2bfloat16(av.z - __bfloat162float(h2)),
            __float2bfloat16(av.w - __bfloat162float(h3)));
        __nv_bfloat16 g0, g1, g2, g3;
        *(__nv_bfloat162*)&sB[0][0][bsoff] = bfhi2(bv.x, bv.y, g0, g1);
        *(__nv_bfloat162*)&sB[0][0][bsoff + 2] = bfhi2(bv.z, bv.w, g2, g3);
        *(__nv_bfloat162*)&sB[0][1][bsoff] = __nv_bfloat162(
            __float2bfloat16(bv.x - __bfloat162float(g0)),
            __float2bfloat16(bv.y - __bfloat162float(g1)));
        *(__nv_bfloat162*)&sB[0][1][bsoff + 2] = __nv_bfloat162(
            __float2bfloat16(bv.z - __bfloat162float(g2)),
            __float2bfloat16(bv.w - __bfloat162float(g3)));
    }
    __syncthreads();

    for (int it = 0; it < niter; it++) {
        int st = it & 1;
        if (it + 1 < niter) {
            av = *(const float4*)(A + abase + (size_t)(it + 1) * 16);
            if (abias) {
                float4 t = *(const float4*)(abias + (it + 1) * 16 + acol);
                av.x += t.x; av.y += t.y; av.z += t.z; av.w += t.w;
            }
            bv = *(const float4*)(B + (size_t)((it + 1) * 16 + bkrow) * N + bn + bncol);
        }
        uint32_t fa[2][2][4], fb[2][2][4];
#pragma unroll
        for (int mt = 0; mt < 2; mt++)
#pragma unroll
            for (int op = 0; op < 2; op++) {
                uint32_t ad = (uint32_t)__cvta_generic_to_shared(
                    &sA[st][op][(wm * 32 + mt * 16 + alrow) * DSTRIDE + alcol]);
                LDSM4(fa[mt][op], ad);
            }
#pragma unroll
        for (int np = 0; np < 2; np++)
#pragma unroll
            for (int op = 0; op < 2; op++) {
                uint32_t ad = (uint32_t)__cvta_generic_to_shared(
                    &sB[st][op][blrow * BPAD + wn * 32 + np * 16 + blcol]);
                LDSM4T(fb[np][op], ad);
            }
#pragma unroll
        for (int mt = 0; mt < 2; mt++)
#pragma unroll
            for (int np = 0; np < 2; np++)
#pragma unroll
                for (int s = 0; s < 2; s++) {
                    int nt = np * 2 + s;
                    MMA16816(acc[mt][nt], fa[mt][0], fb[np][0][2 * s], fb[np][0][2 * s + 1]);
                    MMA16816(acc[mt][nt], fa[mt][0], fb[np][1][2 * s], fb[np][1][2 * s + 1]);
                    MMA16816(acc[mt][nt], fa[mt][1], fb[np][0][2 * s], fb[np][0][2 * s + 1]);
                }
        if (it + 1 < niter) {
            int ns = st ^ 1;
            __nv_bfloat16 h0, h1, h2, h3;
            *(__nv_bfloat162*)&sA[ns][0][asoff] = bfhi2(av.x, av.y, h0, h1);
            *(__nv_bfloat162*)&sA[ns][0][asoff + 2] = bfhi2(av.z, av.w, h2, h3);
            *(__nv_bfloat162*)&sA[ns][1][asoff] = __nv_bfloat162(
                __float2bfloat16(av.x - __bfloat162float(h0)),
                __float2bfloat16(av.y - __bfloat162float(h1)));
            *(__nv_bfloat162*)&sA[ns][1][asoff + 2] = __nv_bfloat162(
                __float2bfloat16(av.z - __bfloat162float(h2)),
                __float2bfloat16(av.w - __bfloat162float(h3)));
            __nv_bfloat16 g0, g1, g2, g3;
            *(__nv_bfloat162*)&sB[ns][0][bsoff] = bfhi2(bv.x, bv.y, g0, g1);
            *(__nv_bfloat162*)&sB[ns][0][bsoff + 2] = bfhi2(bv.z, bv.w, g2, g3);
            *(__nv_bfloat162*)&sB[ns][1][bsoff] = __nv_bfloat162(
                __float2bfloat16(bv.x - __bfloat162float(g0)),
                __float2bfloat16(bv.y - __bfloat162float(g1)));
            *(__nv_bfloat162*)&sB[ns][1][bsoff + 2] = __nv_bfloat162(
                __float2bfloat16(bv.z - __bfloat162float(g2)),
                __float2bfloat16(bv.w - __bfloat162float(g3)));
        }
        __syncthreads();
    }

    // epilogue
#pragma unroll
    for (int mt = 0; mt < 2; mt++) {
        int r0 = bm + wm * 32 + mt * 16 + (lane >> 2);
#pragma unroll
        for (int nt = 0; nt < 4; nt++) {
            int cc = bn + wn * 32 + nt * 8 + (lane & 3) * 2;
            float2 v0 = {acc[mt][nt][0], acc[mt][nt][1]};
            float2 v1 = {acc[mt][nt][2], acc[mt][nt][3]};
            if (cbias) {
                float cb0 = cbias[cc], cb1 = cbias[cc + 1];
                v0.x += cb0; v0.y += cb1;
                v1.x += cb0; v1.y += cb1;
            }
            size_t p0 = (size_t)r0 * N + cc;
            size_t p1 = (size_t)(r0 + 8) * N + cc;
            *(float2*)(C + p0) = v0;
            *(float2*)(C + p1) = v1;
            if (ohi) {
                __nv_bfloat16 a0 = __float2bfloat16(v0.x), a1 = __float2bfloat16(v0.y);
                __nv_bfloat16 b0 = __float2bfloat16(v1.x), b1 = __float2bfloat16(v1.y);
                *(__nv_bfloat162*)(ohi + p0) = __nv_bfloat162(a0, a1);
                *(__nv_bfloat162*)(ohi + p1) = __nv_bfloat162(b0, b1);
                *(__nv_bfloat162*)(olo + p0) = __nv_bfloat162(
                    __float2bfloat16(v0.x - __bfloat162float(a0)),
                    __float2bfloat16(v0.y - __bfloat162float(a1)));
                *(__nv_bfloat162*)(olo + p1) = __nv_bfloat162(
                    __float2bfloat16(v1.x - __bfloat162float(b0)),
                    __float2bfloat16(v1.y - __bfloat162float(b1)));
            }
        }
    }
}

// ---------------- NT GEMM via bf16x3 mma, symmetric: C = E @ E^T, K=512 --------
__global__ __launch_bounds__(512) void k_dot_mma(
    const __nv_bfloat16* __restrict__ Ehi, const __nv_bfloat16* __restrict__ Elo,
    float* __restrict__ C) {
    __shared__ __nv_bfloat16 sA[2][2][128 * DSTRIDE];  // [stage][hi/lo]
    __shared__ __nv_bfloat16 sB[2][2][128 * DSTRIDE];
    int tid = threadIdx.x;
    int lane = tid & 31, wid = tid >> 5;
    int wm = wid >> 2, wn = wid & 3;  // 4x4 warps, 32x32 tile each

    // triangular block decode: blockIdx.x in [0, 64*65/2)
    int bid = blockIdx.x;
    int brow = (int)((sqrtf(8.0f * (float)bid + 1.0f) - 1.0f) * 0.5f);
    while ((brow + 1) * (brow + 2) / 2 <= bid) brow++;
    while (brow * (brow + 1) / 2 > bid) brow--;
    int bcol = bid - brow * (brow + 1) / 2;
    int bi = brow * 128, bj = bcol * 128;  // bi >= bj

    int grow = tid >> 2;
    int gcol = (tid & 3) * 4;
    const __nv_bfloat16* pAhi = Ehi + (size_t)(bi + grow) * EMBD + gcol;
    const __nv_bfloat16* pAlo = Elo + (size_t)(bi + grow) * EMBD + gcol;
    const __nv_bfloat16* pBhi = Ehi + (size_t)(bj + grow) * EMBD + gcol;
    const __nv_bfloat16* pBlo = Elo + (size_t)(bj + grow) * EMBD + gcol;
    int soff = grow * DSTRIDE + gcol;

    int lrow = (lane & 7) + ((lane >> 3) & 1) * 8;
    int lcol = (lane >> 4) * 8;

    float acc[2][4][4];
#pragma unroll
    for (int m = 0; m < 2; m++)
#pragma unroll
        for (int n = 0; n < 4; n++)
#pragma unroll
            for (int q = 0; q < 4; q++) acc[m][n][q] = 0.f;

    uint2 vah = *(const uint2*)pAhi;
    uint2 val = *(const uint2*)pAlo;
    uint2 vbh = *(const uint2*)pBhi;
    uint2 vbl = *(const uint2*)pBlo;
    *(uint2*)&sA[0][0][soff] = vah;
    *(uint2*)&sA[0][1][soff] = val;
    *(uint2*)&sB[0][0][soff] = vbh;
    *(uint2*)&sB[0][1][soff] = vbl;
    vah = *(const uint2*)(pAhi + 16);
    val = *(const uint2*)(pAlo + 16);
    vbh = *(const uint2*)(pBhi + 16);
    vbl = *(const uint2*)(pBlo + 16);
    __syncthreads();

    for (int it = 0; it < EMBD / 16; it++) {
        int st = it & 1;
        uint32_t fa[2][2][4], fb[2][2][4];
#pragma unroll
        for (int mt = 0; mt < 2; mt++)
#pragma unroll
            for (int op = 0; op < 2; op++) {
                uint32_t ad = (uint32_t)__cvta_generic_to_shared(
                    &sA[st][op][(wm * 32 + mt * 16 + lrow) * DSTRIDE + lcol]);
                LDSM4(fa[mt][op], ad);
            }
#pragma unroll
        for (int np = 0; np < 2; np++)
#pragma unroll
            for (int op = 0; op < 2; op++) {
                uint32_t ad = (uint32_t)__cvta_generic_to_shared(
                    &sB[st][op][(wn * 32 + np * 16 + lrow) * DSTRIDE + lcol]);
                LDSM4(fb[np][op], ad);
            }
        if (it < EMBD / 16 - 1) {
            int ns = st ^ 1;
            *(uint2*)&sA[ns][0][soff] = vah;
            *(uint2*)&sA[ns][1][soff] = val;
            *(uint2*)&sB[ns][0][soff] = vbh;
            *(uint2*)&sB[ns][1][soff] = vbl;
        }
        __syncthreads();
        if (it < EMBD / 16 - 2) {
            vah = *(const uint2*)(pAhi + (it + 2) * 16);
            val = *(const uint2*)(pAlo + (it + 2) * 16);
            vbh = *(const uint2*)(pBhi + (it + 2) * 16);
            vbl = *(const uint2*)(pBlo + (it + 2) * 16);
        }
#pragma unroll
        for (int mt = 0; mt < 2; mt++)
#pragma unroll
            for (int np = 0; np < 2; np++)
#pragma unroll
                for (int s = 0; s < 2; s++) {
                    int nt = np * 2 + s;
                    MMA16816(acc[mt][nt], fa[mt][0], fb[np][0][s], fb[np][0][2 + s]);
                    MMA16816(acc[mt][nt], fa[mt][0], fb[np][1][s], fb[np][1][2 + s]);
                    MMA16816(acc[mt][nt], fa[mt][1], fb[np][0][s], fb[np][0][2 + s]);
                }
    }

    // epilogue: direct tile + mirrored (transposed) tile for off-diagonal blocks
#pragma unroll
    for (int mt = 0; mt < 2; mt++) {
        int r0 = bi + wm * 32 + mt * 16 + (lane >> 2);
#pragma unroll
        for (int nt = 0; nt < 4; nt++) {
            int cc = bj + wn * 32 + nt * 8 + (lane & 3) * 2;
            float2 v0 = {acc[mt][nt][0], acc[mt][nt][1]};
            float2 v1 = {acc[mt][nt][2], acc[mt][nt][3]};
            *(float2*)(C + (size_t)r0 * BB + cc) = v0;
            *(float2*)(C + (size_t)(r0 + 8) * BB + cc) = v1;
            if (bi != bj) {
                C[(size_t)cc * BB + r0] = acc[mt][nt][0];
                C[(size_t)(cc + 1) * BB + r0] = acc[mt][nt][1];
                C[(size_t)cc * BB + r0 + 8] = acc[mt][nt][2];
                C[(size_t)(cc + 1) * BB + r0 + 8] = acc[mt][nt][3];
            }
        }
    }
}

// skip connection + interpolation accumulate
__global__ void k_accum(const float* __restrict__ out0, const int* __restrict__ res,
                        const float* __restrict__ gat1, const float* __restrict__ masks,
                        const float* __restrict__ iw, int mod, float* __restrict__ acc) {
    int b = blockIdx.x;
    int t = threadIdx.x;
    __shared__ float coef;
    __shared__ int rid;
    if (t == 0) {
        float w0 = iw[0], w1 = iw[1], w2 = iw[2];
        float mw = fmaxf(w0, fmaxf(w1, w2));
        float e0 = expf(w0 - mw), e1 = expf(w1 - mw), e2 = expf(w2 - mw);
        float ws = e0 + e1 + e2;
        float wi = (mod == 0 ? e0 : (mod == 1 ? e1 : e2)) / ws;
        float m0 = masks[b * 3 + 0], m1 = masks[b * 3 + 1], m2 = masks[b * 3 + 2];
        float msum = m0 + m1 + m2;
        float r = 1.0f + 1.0f / powf(1.0f + 3.0f, 20.0f) + 1.0f / powf(msum, 20.0f);
        r = floorf(r);
        r = r / (r + 1e-10f);
        float z0 = m0 * r, z1 = m1 * r, z2 = m2 * r;
        z0 = z0 + (1.0f - z0) * (-1e10f);
        z1 = z1 + (1.0f - z1) * (-1e10f);
        z2 = z2 + (1.0f - z2) * (-1e10f);
        float zm = fmaxf(z0, fmaxf(z1, z2));
        float x0 = expf(z0 - zm), x1 = expf(z1 - zm), x2 = expf(z2 - zm);
        float xs = x0 + x1 + x2;
        float im = (mod == 0 ? x0 : (mod == 1 ? x1 : x2)) / xs;
        coef = wi * im;
        rid = res[b];
    }
    __syncthreads();
    acc[(size_t)b * HID + t] += coef * (out0[(size_t)rid * HID + t] + gat1[(size_t)b * HID + t]);
}

__global__ void k_weights(const float* __restrict__ iw, float* __restrict__ o) {
    float w0 = iw[0], w1 = iw[1], w2 = iw[2];
    float m = fmaxf(w0, fmaxf(w1, w2));
    float e0 = expf(w0 - m), e1 = expf(w1 - m), e2 = expf(w2 - m);
    float s = e0 + e1 + e2;
    o[0] = e0 / s; o[1] = e1 / s; o[2] = e2 / s;
}

extern "C" void kernel_launch(void* const* d_in, const int* in_sizes, int n_in,
                              void* d_out, int out_size) {
    const int*   n_id     = (const int*)d_in[0];
    const int*   src0     = (const int*)d_in[1];
    const int*   dst0     = (const int*)d_in[2];
    const int*   src1     = (const int*)d_in[3];
    const int*   dst1     = (const int*)d_in[4];
    const int*   res_n_id = (const int*)d_in[5];
    const float* vals0    = (const float*)d_in[6];
    const float* vals1    = (const float*)d_in[7];
    const float* masks    = (const float*)d_in[8];
    const float* pre_W    = (const float*)d_in[9];
    const float* pre_b    = (const float*)d_in[10];
    const float* W_gat    = (const float*)d_in[11];
    const float* att      = (const float*)d_in[12];
    const float* gat_b    = (const float*)d_in[13];
    const float* interp_w = (const float*)d_in[14];
    const float* emb_W    = (const float*)d_in[15];
    const float* emb_b    = (const float*)d_in[16];

    float* dot = (float*)d_out;
    float* emb = dot + (size_t)BB * BB;
    float* wout = emb + (size_t)BB * EMBD;

    float *h, *s, *out0, *gat1, *acc, *c;
    int *cnt, *indptr, *wp, *order, *blksum;
    __nv_bfloat16 *ehi, *elo;
    cudaGetSymbolAddress((void**)&h, g_h);
    cudaGetSymbolAddress((void**)&s, g_s);
    cudaGetSymbolAddress((void**)&out0, g_out0);
    cudaGetSymbolAddress((void**)&gat1, g_gat1);
    cudaGetSymbolAddress((void**)&acc, g_acc);
    cudaGetSymbolAddress((void**)&c, g_c);
    cudaGetSymbolAddress((void**)&cnt, g_cnt);
    cudaGetSymbolAddress((void**)&indptr, g_indptr);
    cudaGetSymbolAddress((void**)&wp, g_wp);
    cudaGetSymbolAddress((void**)&order, g_order);
    cudaGetSymbolAddress((void**)&blksum, g_blksum);
    cudaGetSymbolAddress((void**)&ehi, g_ehi);
    cudaGetSymbolAddress((void**)&elo, g_elo);

    k_zero_f<<<(BB * HID + 255) / 256, 256>>>(acc, BB * HID);

    // ---- batched CSR build for all 6 graphs ----
    k_zero_i<<<(TSEG + 255) / 256, 256>>>(cnt, TSEG);
    k_hist_all<<<(TEDG + 255) / 256, 256>>>(dst0, dst1, cnt);
    k_scan1<<<NSCANB, 1024>>>(cnt, TSEG, indptr, blksum);
    k_scan2<<<1, 128>>>(blksum, NSCANB, indptr, TSEG);
    k_scan3<<<(TSEG + 255) / 256, 256>>>(indptr, wp, blksum, TSEG);
    k_scatter_all<<<(TEDG + 255) / 256, 256>>>(dst0, dst1, wp, order);
    k_sortseg<<<(TSEG + 255) / 256, 256>>>(indptr, TSEG, order);

    const int IN_SZ = 50000;
    for (int i = 0; i < MODS; i++) {
        const float* Wg  = W_gat + (size_t)i * HID * HID;
        const float* ai  = att + (size_t)i * HID;
        const float* gbi = gat_b + (size_t)i * HID;
        const int* ip0 = indptr + i * (NN1 + BB);
        const int* ip1 = indptr + i * (NN1 + BB) + NN1;

        // ---- block 0: N0 sources -> N1 targets ----
        const int* s0 = src0 + (size_t)i * EE0;
        {   // h0 = (pre_W[i][n_id] + pre_b[i]) @ Wg
            dim3 grid(HID / 128, NN0 / 128);
            k_gemm_mma<<<grid, 512>>>(pre_W + (size_t)i * IN_SZ * HID,
                                      n_id + (size_t)i * NN0,
                                      pre_b + (size_t)i * HID,
                                      Wg, nullptr, h, NN0, HID, HID,
                                      nullptr, nullptr);
        }
        k_score<<<NN0, 256>>>(h, ai, s);
        k_coef<<<(NN1 * 32 + 255) / 256, 256>>>(order, ip0, s0,
                                                vals0 + (size_t)i * EE0, s, c, NN1);
        k_reduce<<<NN1, 256>>>(order, ip0, s0, c, h, gbi, out0);

        // ---- block 1: N1 sources -> B targets ----
        const int* s1 = src1 + (size_t)i * EE1;
        {   // h1 = out0 @ Wg
            dim3 grid(HID / 128, NN1 / 128);
            k_gemm_mma<<<grid, 512>>>(out0, nullptr, nullptr, Wg, nullptr, h,
                                      NN1, HID, HID, nullptr, nullptr);
        }
        k_score<<<NN1, 256>>>(h, ai, s);
        k_coef<<<(BB * 32 + 255) / 256, 256>>>(order, ip1, s1,
                                               vals1 + (size_t)i * EE1, s, c, BB);
        k_reduce<<<BB, 256>>>(order, ip1, s1, c, h, gbi, gat1);

        // ---- skip + interpolation accumulate ----
        k_accum<<<BB, 256>>>(out0, res_n_id + (size_t)i * BB, gat1, masks,
                             interp_w, i, acc);
    }

    // emb = acc @ emb_W + emb_b  (+ fused bf16 hi/lo split)
    {
        dim3 grid(EMBD / 128, BB / 128);
        k_gemm_mma<<<grid, 512>>>(acc, nullptr, nullptr, emb_W, emb_b, emb,
                                  BB, EMBD, HID, ehi, elo);
    }
    // dot = emb @ emb^T via bf16x3 tensor-core emulation, symmetric half-grid
    {
        int npairs = (BB / 128) * (BB / 128 + 1) / 2;  // 2080
        k_dot_mma<<<npairs, 512>>>(ehi, elo, dot);
    }
    k_weights<<<1, 1>>>(interp_w, wout);
}